// round 1
// baseline (speedup 1.0000x reference)
#include <cuda_runtime.h>
#include <math.h>

// Problem constants
#define Bb    2
#define Ss    2048
#define HIDD  2048
#define Hh    16
#define DHh   128
#define NBLK  32        // 2048 / 64
#define MROWS 4096      // B*S
#define SCALE_F 0.08838834764831845f   // 1/sqrt(128)

// ---------------- scratch (static device allocations) ----------------
__device__ float g_q[(size_t)MROWS * HIDD];
__device__ float g_k[(size_t)MROWS * HIDD];
__device__ float g_v[(size_t)MROWS * HIDD];
__device__ float g_ctx[(size_t)MROWS * HIDD];
__device__ unsigned char g_mask[(size_t)Ss * Ss];
__device__ unsigned char g_bany[NBLK * NBLK];
__device__ int g_flag;

// ---------------- mask dtype detection + canonicalization ----------------
// mask[0][0] and mask[0][1] are both True (global row 0).
//   u8  layout: bytes 0,1 == 1,1
//   i32 layout: bytes 0..7 == 01 00 00 00 01 00 00 00  -> byte1 == 0, byte0 == 1
//   f32 layout: 1.0f = 00 00 80 3f                     -> byte0 == 0
__global__ void detect_kernel(const unsigned char* __restrict__ raw) {
    int f;
    if (raw[0] == 1 && raw[1] == 1) f = 0;       // u8 / bool
    else if (raw[0] == 1)           f = 1;       // int32
    else                            f = 2;       // float32
    g_flag = f;
}

__global__ void expand_kernel(const void* __restrict__ raw) {
    size_t idx = (size_t)blockIdx.x * blockDim.x + threadIdx.x;
    if (idx >= (size_t)Ss * Ss) return;
    int f = g_flag;
    unsigned char v;
    if (f == 0)      v = ((const unsigned char*)raw)[idx] != 0;
    else if (f == 1) v = ((const int*)raw)[idx] != 0;
    else             v = ((const float*)raw)[idx] != 0.0f;
    g_mask[idx] = v;
}

// block-any table: g_bany[qb][kb] = any(mask[qb*64:+64, kb*64:+64])
__global__ void bany_kernel() {
    int qb = blockIdx.y, kb = blockIdx.x;
    int r = threadIdx.x;   // 64 threads
    const unsigned char* row = &g_mask[(size_t)(qb * 64 + r) * Ss + kb * 64];
    int any = 0;
    #pragma unroll 8
    for (int c = 0; c < 64; c++) any |= row[c];
    int res = __syncthreads_or(any);
    if (r == 0) g_bany[qb * NBLK + kb] = res ? 1 : 0;
}

// ---------------- SIMT fp32 GEMM: C[M,N] = A[M,K] @ B[K,N] ----------------
// 128x128 tile, BK=16, 256 threads, 8x8 per-thread microtile.
__global__ __launch_bounds__(256, 2)
void sgemm_kernel(const float* __restrict__ A, const float* __restrict__ B,
                  float* __restrict__ C, int M, int N, int K) {
    __shared__ float As[16][128];   // k-major (transposed at load)
    __shared__ float Bs[16][128];

    int tid = threadIdx.x;
    int tx = tid & 15, ty = tid >> 4;
    int bm = blockIdx.y * 128, bn = blockIdx.x * 128;

    float acc[8][8];
    #pragma unroll
    for (int i = 0; i < 8; i++)
        #pragma unroll
        for (int j = 0; j < 8; j++) acc[i][j] = 0.0f;

    const float* Ab = A + (size_t)bm * K;
    const float* Bp = B + bn;

    for (int k0 = 0; k0 < K; k0 += 16) {
        // A tile: 128 rows x 16 k -> 512 float4, 2 per thread; store transposed
        #pragma unroll
        for (int i = 0; i < 2; i++) {
            int vec = tid + i * 256;
            int m = vec >> 2;
            int k4 = (vec & 3) * 4;
            float4 a = *(const float4*)&Ab[(size_t)m * K + k0 + k4];
            As[k4 + 0][m] = a.x; As[k4 + 1][m] = a.y;
            As[k4 + 2][m] = a.z; As[k4 + 3][m] = a.w;
        }
        // B tile: 16 rows x 128 n -> 512 float4, coalesced direct copy
        #pragma unroll
        for (int i = 0; i < 2; i++) {
            int vec = tid + i * 256;
            int k = vec >> 5;
            int n4 = (vec & 31) * 4;
            *(float4*)&Bs[k][n4] = *(const float4*)&Bp[(size_t)(k0 + k) * N + n4];
        }
        __syncthreads();

        #pragma unroll
        for (int kk = 0; kk < 16; kk++) {
            float a[8], b[8];
            *(float4*)&a[0] = *(float4*)&As[kk][ty * 8];
            *(float4*)&a[4] = *(float4*)&As[kk][ty * 8 + 4];
            *(float4*)&b[0] = *(float4*)&Bs[kk][tx * 8];
            *(float4*)&b[4] = *(float4*)&Bs[kk][tx * 8 + 4];
            #pragma unroll
            for (int i = 0; i < 8; i++)
                #pragma unroll
                for (int j = 0; j < 8; j++)
                    acc[i][j] += a[i] * b[j];
        }
        __syncthreads();
    }

    #pragma unroll
    for (int i = 0; i < 8; i++) {
        int m = bm + ty * 8 + i;
        float* crow = &C[(size_t)m * N + bn + tx * 8];
        *(float4*)&crow[0] = *(float4*)&acc[i][0];
        *(float4*)&crow[4] = *(float4*)&acc[i][4];
    }
}

// ---------------- fused masked flash attention ----------------
// grid: (S/64, H, B), 256 threads/CTA.
// Dynamic smem layout (floats):
//   sQ   [64][128]          8192
//   sKT  [128][65] / sV[64][128]   8320 (union; V fits in 8192)
//   sS   [64][65]           4160
//   gM[64], gL[64], gSc[64]  192
//   sMask 64*64 bytes       1024 floats worth
// total 21888 floats = 87552 bytes
#define ATTN_SMEM_BYTES 87552

__global__ __launch_bounds__(256, 2)
void attn_kernel() {
    extern __shared__ float sm[];
    float* sQ  = sm;                       // 8192
    float* sKT = sm + 8192;                // 8320 (K^T) / reused as sV [64][128]
    float* sS  = sm + 8192 + 8320;         // 4160
    float* gM  = sS + 4160;
    float* gL  = gM + 64;
    float* gSc = gL + 64;
    unsigned char* sMask = (unsigned char*)(gSc + 64);   // 4096 bytes

    int tid = threadIdx.x;
    int qb = blockIdx.x, h = blockIdx.y, b = blockIdx.z;
    int tx = tid & 15, ty = tid >> 4;

    // load Q tile (64 rows x 128)
    {
        const float* Qg = g_q + ((size_t)(b * Ss + qb * 64)) * HIDD + h * DHh;
        #pragma unroll
        for (int i = 0; i < 8; i++) {
            int vec = tid + i * 256;
            int r = vec >> 5, c4 = (vec & 31) * 4;
            *(float4*)&sQ[r * 128 + c4] = *(const float4*)&Qg[(size_t)r * HIDD + c4];
        }
    }
    if (tid < 64) { gM[tid] = -1e30f; gL[tid] = 0.0f; }

    float o[4][8];
    #pragma unroll
    for (int i = 0; i < 4; i++)
        #pragma unroll
        for (int j = 0; j < 8; j++) o[i][j] = 0.0f;
    __syncthreads();

    for (int kb = 0; kb < NBLK; kb++) {
        if (!g_bany[qb * NBLK + kb]) continue;   // uniform branch

        // ---- load K (transposed) + mask tile ----
        const float* Kg = g_k + ((size_t)(b * Ss + kb * 64)) * HIDD + h * DHh;
        #pragma unroll
        for (int i = 0; i < 8; i++) {
            int vec = tid + i * 256;
            int r = vec >> 5, c4 = (vec & 31) * 4;
            float4 kv = *(const float4*)&Kg[(size_t)r * HIDD + c4];
            sKT[(c4 + 0) * 65 + r] = kv.x;
            sKT[(c4 + 1) * 65 + r] = kv.y;
            sKT[(c4 + 2) * 65 + r] = kv.z;
            sKT[(c4 + 3) * 65 + r] = kv.w;
        }
        {
            const unsigned char* Mg = g_mask + (size_t)(qb * 64) * Ss + kb * 64;
            int r = tid >> 2, off = (tid & 3) * 16;
            *(int4*)&sMask[r * 64 + off] = *(const int4*)&Mg[(size_t)r * Ss + off];
        }
        __syncthreads();

        // ---- scores: S = Q @ K^T, mask, scale ----
        {
            int sr0 = ty * 4, sc0 = tx * 4;
            float acc[4][4];
            #pragma unroll
            for (int i = 0; i < 4; i++)
                #pragma unroll
                for (int j = 0; j < 4; j++) acc[i][j] = 0.0f;
            #pragma unroll 4
            for (int kk = 0; kk < 128; kk++) {
                float qv[4], kv[4];
                #pragma unroll
                for (int i = 0; i < 4; i++) qv[i] = sQ[(sr0 + i) * 128 + kk];
                #pragma unroll
                for (int j = 0; j < 4; j++) kv[j] = sKT[kk * 65 + sc0 + j];
                #pragma unroll
                for (int i = 0; i < 4; i++)
                    #pragma unroll
                    for (int j = 0; j < 4; j++) acc[i][j] += qv[i] * kv[j];
            }
            #pragma unroll
            for (int i = 0; i < 4; i++)
                #pragma unroll
                for (int j = 0; j < 4; j++) {
                    float v = sMask[(sr0 + i) * 64 + sc0 + j]
                              ? acc[i][j] * SCALE_F : -1e30f;
                    sS[(sr0 + i) * 65 + sc0 + j] = v;
                }
        }
        __syncthreads();

        // ---- load V into sKT region (normal [64][128] layout) + online softmax ----
        float* sV = sKT;
        {
            const float* Vg = g_v + ((size_t)(b * Ss + kb * 64)) * HIDD + h * DHh;
            #pragma unroll
            for (int i = 0; i < 8; i++) {
                int vec = tid + i * 256;
                int r = vec >> 5, c4 = (vec & 31) * 4;
                *(float4*)&sV[r * 128 + c4] = *(const float4*)&Vg[(size_t)r * HIDD + c4];
            }
        }
        {
            int row = tid >> 2, seg = tid & 3;   // 4 lanes per row, 16 cols each
            float* srow = &sS[row * 65 + seg * 16];
            float mx = -1e30f;
            #pragma unroll
            for (int c = 0; c < 16; c++) mx = fmaxf(mx, srow[c]);
            mx = fmaxf(mx, __shfl_xor_sync(0xffffffffu, mx, 1));
            mx = fmaxf(mx, __shfl_xor_sync(0xffffffffu, mx, 2));
            float m_old = gM[row];
            float m_new = fmaxf(m_old, mx);
            float s = 0.0f;
            #pragma unroll
            for (int c = 0; c < 16; c++) {
                float p = __expf(srow[c] - m_new);
                srow[c] = p;
                s += p;
            }
            s += __shfl_xor_sync(0xffffffffu, s, 1);
            s += __shfl_xor_sync(0xffffffffu, s, 2);
            if (seg == 0) {
                float sc = __expf(m_old - m_new);
                gL[row] = gL[row] * sc + s;
                gM[row] = m_new;
                gSc[row] = sc;
            }
        }
        __syncthreads();

        // ---- O = O * scale + P @ V ----
        {
            int r0 = ty * 4, c0 = tx * 8;
            #pragma unroll
            for (int i = 0; i < 4; i++) {
                float sc = gSc[r0 + i];
                #pragma unroll
                for (int j = 0; j < 8; j++) o[i][j] *= sc;
            }
            #pragma unroll 2
            for (int kk = 0; kk < 64; kk++) {
                float p[4], vv[8];
                #pragma unroll
                for (int i = 0; i < 4; i++) p[i] = sS[(r0 + i) * 65 + kk];
                *(float4*)&vv[0] = *(float4*)&sV[kk * 128 + c0];
                *(float4*)&vv[4] = *(float4*)&sV[kk * 128 + c0 + 4];
                #pragma unroll
                for (int i = 0; i < 4; i++)
                    #pragma unroll
                    for (int j = 0; j < 8; j++) o[i][j] += p[i] * vv[j];
            }
        }
        __syncthreads();
    }

    // epilogue: O /= l, write ctx
    {
        int r0 = ty * 4, c0 = tx * 8;
        float* Cg = g_ctx + ((size_t)(b * Ss + qb * 64)) * HIDD + h * DHh;
        #pragma unroll
        for (int i = 0; i < 4; i++) {
            float inv = 1.0f / gL[r0 + i];
            float tmp[8];
            #pragma unroll
            for (int j = 0; j < 8; j++) tmp[j] = o[i][j] * inv;
            *(float4*)&Cg[(size_t)(r0 + i) * HIDD + c0]     = *(float4*)&tmp[0];
            *(float4*)&Cg[(size_t)(r0 + i) * HIDD + c0 + 4] = *(float4*)&tmp[4];
        }
    }
}

// ---------------- launch ----------------
extern "C" void kernel_launch(void* const* d_in, const int* in_sizes, int n_in,
                              void* d_out, int out_size) {
    const float* X  = (const float*)d_in[0];   // (B,S,HID)
    const float* Wq = (const float*)d_in[1];
    const float* Wk = (const float*)d_in[2];
    const float* Wv = (const float*)d_in[3];
    const float* Wo = (const float*)d_in[4];
    const void*  Mraw = d_in[5];               // bool mask, dtype-detected
    float* out = (float*)d_out;

    cudaFuncSetAttribute(attn_kernel,
                         cudaFuncAttributeMaxDynamicSharedMemorySize,
                         ATTN_SMEM_BYTES);

    // mask canonicalization
    detect_kernel<<<1, 1>>>((const unsigned char*)Mraw);
    expand_kernel<<<(Ss * Ss) / 256, 256>>>(Mraw);
    bany_kernel<<<dim3(NBLK, NBLK), 64>>>();

    // scratch pointers to __device__ symbols
    float *pq, *pk, *pv, *pctx;
    cudaGetSymbolAddress((void**)&pq,   g_q);
    cudaGetSymbolAddress((void**)&pk,   g_k);
    cudaGetSymbolAddress((void**)&pv,   g_v);
    cudaGetSymbolAddress((void**)&pctx, g_ctx);

    dim3 gemm_grid(HIDD / 128, MROWS / 128);   // (16, 32)
    sgemm_kernel<<<gemm_grid, 256>>>(X, Wq, pq, MROWS, HIDD, HIDD);
    sgemm_kernel<<<gemm_grid, 256>>>(X, Wk, pk, MROWS, HIDD, HIDD);
    sgemm_kernel<<<gemm_grid, 256>>>(X, Wv, pv, MROWS, HIDD, HIDD);

    attn_kernel<<<dim3(Ss / 64, Hh, Bb), 256, ATTN_SMEM_BYTES>>>();

    sgemm_kernel<<<gemm_grid, 256>>>(pctx, Wo, out, MROWS, HIDD, HIDD);
}

// round 3
// speedup vs baseline: 2.1018x; 2.1018x over previous
#include <cuda_runtime.h>
#include <cuda_bf16.h>
#include <stdint.h>
#include <math.h>

// Problem constants
#define Bb    2
#define Ss    2048
#define HIDD  2048
#define Hh    16
#define DHh   128
#define NBLK  32        // 2048 / 64
#define MROWS 4096      // B*S
#define SCALE_F 0.08838834764831845f   // 1/sqrt(128)

// ---------------- scratch (static device allocations) ----------------
__device__ float g_q[(size_t)MROWS * HIDD];
__device__ float g_k[(size_t)MROWS * HIDD];
__device__ float g_v[(size_t)MROWS * HIDD];
__device__ float g_ctx[(size_t)MROWS * HIDD];
__device__ __nv_bfloat16 g_xhi[(size_t)MROWS * HIDD];
__device__ __nv_bfloat16 g_xlo[(size_t)MROWS * HIDD];
__device__ __nv_bfloat16 g_chi[(size_t)MROWS * HIDD];
__device__ __nv_bfloat16 g_clo[(size_t)MROWS * HIDD];
__device__ __nv_bfloat16 g_wthi[4][(size_t)HIDD * HIDD];   // W^T [N][K] hi
__device__ __nv_bfloat16 g_wtlo[4][(size_t)HIDD * HIDD];   // W^T [N][K] lo
__device__ unsigned char g_mask[(size_t)Ss * Ss];
__device__ unsigned char g_bany[NBLK * NBLK];
__device__ int g_flag;

// ======================= PTX helpers (family-portable) =======================
__device__ __forceinline__ uint32_t smem_u32(const void* p) {
    uint32_t a;
    asm("{ .reg .u64 t; cvta.to.shared.u64 t, %1; cvt.u32.u64 %0, t; }"
        : "=r"(a) : "l"(p));
    return a;
}
__device__ __forceinline__ void cp_async16(uint32_t dst, const void* src) {
    asm volatile("cp.async.cg.shared.global [%0], [%1], 16;"
                 :: "r"(dst), "l"(src) : "memory");
}
#define CP_COMMIT() asm volatile("cp.async.commit_group;" ::: "memory")
#define CP_WAIT(n)  asm volatile("cp.async.wait_group %0;" :: "n"(n) : "memory")

__device__ __forceinline__ void ldsm4(uint32_t* r, uint32_t addr) {
    asm volatile("ldmatrix.sync.aligned.m8n8.x4.shared.b16 {%0,%1,%2,%3}, [%4];"
                 : "=r"(r[0]), "=r"(r[1]), "=r"(r[2]), "=r"(r[3]) : "r"(addr));
}
__device__ __forceinline__ void mma16816(float* c, const uint32_t* a, const uint32_t* b) {
    asm volatile(
        "mma.sync.aligned.m16n8k16.row.col.f32.bf16.bf16.f32 "
        "{%0,%1,%2,%3}, {%4,%5,%6,%7}, {%8,%9}, {%0,%1,%2,%3};"
        : "+f"(c[0]), "+f"(c[1]), "+f"(c[2]), "+f"(c[3])
        : "r"(a[0]), "r"(a[1]), "r"(a[2]), "r"(a[3]), "r"(b[0]), "r"(b[1]));
}

#define SW128(o) ((o) ^ (((o) >> 3) & 0x70))

// ---------------- mask dtype detection + canonicalization ----------------
__global__ void detect_kernel(const unsigned char* __restrict__ raw) {
    int f;
    if (raw[0] == 1 && raw[1] == 1) f = 0;       // u8 / bool
    else if (raw[0] == 1)           f = 1;       // int32
    else                            f = 2;       // float32
    g_flag = f;
}

__global__ void expand_kernel(const void* __restrict__ raw) {
    size_t idx = (size_t)blockIdx.x * blockDim.x + threadIdx.x;
    if (idx >= (size_t)Ss * Ss) return;
    int f = g_flag;
    unsigned char v;
    if (f == 0)      v = ((const unsigned char*)raw)[idx] != 0;
    else if (f == 1) v = ((const int*)raw)[idx] != 0;
    else             v = ((const float*)raw)[idx] != 0.0f;
    g_mask[idx] = v;
}

__global__ void bany_kernel() {
    int qb = blockIdx.y, kb = blockIdx.x;
    int r = threadIdx.x;   // 64 threads
    const unsigned char* row = &g_mask[(size_t)(qb * 64 + r) * Ss + kb * 64];
    int any = 0;
    #pragma unroll 8
    for (int c = 0; c < 64; c++) any |= row[c];
    int res = __syncthreads_or(any);
    if (r == 0) g_bany[qb * NBLK + kb] = res ? 1 : 0;
}

// ---------------- fp32 -> bf16 hi/lo split ----------------
__global__ void split_kernel(const float* __restrict__ in,
                             __nv_bfloat16* __restrict__ hi,
                             __nv_bfloat16* __restrict__ lo, int n4) {
    int i = blockIdx.x * blockDim.x + threadIdx.x;
    if (i >= n4) return;
    float4 v = ((const float4*)in)[i];
    __nv_bfloat16 h0 = __float2bfloat16(v.x), h1 = __float2bfloat16(v.y);
    __nv_bfloat16 h2 = __float2bfloat16(v.z), h3 = __float2bfloat16(v.w);
    __nv_bfloat16 l0 = __float2bfloat16(v.x - __bfloat162float(h0));
    __nv_bfloat16 l1 = __float2bfloat16(v.y - __bfloat162float(h1));
    __nv_bfloat16 l2 = __float2bfloat16(v.z - __bfloat162float(h2));
    __nv_bfloat16 l3 = __float2bfloat16(v.w - __bfloat162float(h3));
    ushort4 hv = make_ushort4(__bfloat16_as_ushort(h0), __bfloat16_as_ushort(h1),
                              __bfloat16_as_ushort(h2), __bfloat16_as_ushort(h3));
    ushort4 lv = make_ushort4(__bfloat16_as_ushort(l0), __bfloat16_as_ushort(l1),
                              __bfloat16_as_ushort(l2), __bfloat16_as_ushort(l3));
    ((ushort4*)hi)[i] = hv;
    ((ushort4*)lo)[i] = lv;
}

// ---------------- transpose + split: W[K][N] -> T[N][K] hi/lo ----------------
__global__ void tsplit_kernel(const float* __restrict__ W,
                              __nv_bfloat16* __restrict__ Thi,
                              __nv_bfloat16* __restrict__ Tlo) {
    __shared__ float t[32][33];
    int n0 = blockIdx.x * 32, k0 = blockIdx.y * 32;
    int tx = threadIdx.x, ty = threadIdx.y;   // block (32, 8)
    #pragma unroll
    for (int i = 0; i < 4; i++)
        t[ty + i * 8][tx] = W[(size_t)(k0 + ty + i * 8) * HIDD + n0 + tx];
    __syncthreads();
    #pragma unroll
    for (int i = 0; i < 4; i++) {
        float x = t[tx][ty + i * 8];
        __nv_bfloat16 h = __float2bfloat16(x);
        __nv_bfloat16 l = __float2bfloat16(x - __bfloat162float(h));
        size_t o = (size_t)(n0 + ty + i * 8) * HIDD + k0 + tx;
        Thi[o] = h;
        Tlo[o] = l;
    }
}

// ---------------- HMMA bf16x3 GEMM ----------------
// C[M=4096, N=2048] = A[M,K] @ B^T,  A row-major [M][K], B stored [N][K] (K-major).
// A, B pre-split into bf16 hi/lo.  C += Ahi*Bhi + Ahi*Blo + Alo*Bhi (fp32 regs).
// CTA tile 128x128, K-chunk 64 (SW128 128-byte rows), double-buffered cp.async.
#define GK 2048
#define GN 2048
#define NIT 32                       // 2048 / 64
#define GTILE_BYTES 16384            // 128 rows x 128 bytes
#define GSTAGE (4 * GTILE_BYTES)     // Ahi, Alo, Bhi, Blo
#define GSMEM_TOTAL (2 * GSTAGE)     // 131072

__global__ __launch_bounds__(256, 1)
void gemm_hmma_x3(const __nv_bfloat16* __restrict__ Ahi,
                  const __nv_bfloat16* __restrict__ Alo,
                  const __nv_bfloat16* __restrict__ Bhi,
                  const __nv_bfloat16* __restrict__ Blo,
                  float* __restrict__ C) {
    extern __shared__ char smem[];
    uint32_t sb = smem_u32(smem);
    int tid = threadIdx.x, l = tid & 31, wid = tid >> 5;
    int warp_m = wid & 3, warp_n = wid >> 2;      // 4 x 2 warps, warp tile 32x64
    int bm = blockIdx.y * 128, bn = blockIdx.x * 128;

    const char* src[4] = {
        (const char*)(Ahi + (size_t)bm * GK),
        (const char*)(Alo + (size_t)bm * GK),
        (const char*)(Bhi + (size_t)bn * GK),
        (const char*)(Blo + (size_t)bn * GK)
    };

    float c[2][8][4];
    #pragma unroll
    for (int i = 0; i < 2; i++)
        #pragma unroll
        for (int j = 0; j < 8; j++)
            #pragma unroll
            for (int k = 0; k < 4; k++) c[i][j][k] = 0.0f;

    // staging store offsets (per thread): 4 16B vectors per tile
    int srow[4], scol[4];
    #pragma unroll
    for (int j = 0; j < 4; j++) {
        int v = tid + j * 256;
        srow[j] = v >> 3;
        scol[j] = (v & 7) * 16;
    }

    auto stage_load = [&](int ci, int st) {
        int koff = ci * 128;   // byte offset along K (64 bf16)
        #pragma unroll
        for (int w = 0; w < 4; w++) {
            uint32_t dst = sb + st * GSTAGE + w * GTILE_BYTES;
            const char* s = src[w] + koff;
            #pragma unroll
            for (int j = 0; j < 4; j++) {
                cp_async16(dst + SW128(srow[j] * 128 + scol[j]),
                           s + (size_t)srow[j] * (GK * 2) + scol[j]);
            }
        }
    };

    // ldmatrix lane geometry
    int rrA = (l & 7) + ((l >> 3) & 1) * 8;
    int kbA = ((l >> 4) & 1) * 16;
    int rrB = (l & 7) + ((l >> 4) & 1) * 8;
    int kbB = ((l >> 3) & 1) * 16;

    stage_load(0, 0);
    CP_COMMIT();

    for (int i = 0; i < NIT; i++) {
        if (i + 1 < NIT) {
            stage_load(i + 1, (i + 1) & 1);
            CP_COMMIT();
            CP_WAIT(1);
        } else {
            CP_WAIT(0);
        }
        __syncthreads();

        uint32_t bAh = sb + (i & 1) * GSTAGE;
        uint32_t bAl = bAh + GTILE_BYTES;
        uint32_t bBh = bAh + 2 * GTILE_BYTES;
        uint32_t bBl = bAh + 3 * GTILE_BYTES;

        #pragma unroll
        for (int ks = 0; ks < 4; ks++) {
            int kk = ks * 32;
            uint32_t afh[2][4], afl[2][4];
            #pragma unroll
            for (int mt = 0; mt < 2; mt++) {
                int rb = (warp_m * 32 + mt * 16 + rrA) * 128;
                uint32_t off = rb + ((kk + kbA) ^ ((rb >> 3) & 0x70));
                ldsm4(afh[mt], bAh + off);
                ldsm4(afl[mt], bAl + off);
            }
            uint32_t bfh[8][2], bfl[8][2];
            #pragma unroll
            for (int np = 0; np < 4; np++) {
                int rb = (warp_n * 64 + np * 16 + rrB) * 128;
                uint32_t off = rb + ((kk + kbB) ^ ((rb >> 3) & 0x70));
                uint32_t t[4];
                ldsm4(t, bBh + off);
                bfh[np * 2][0] = t[0]; bfh[np * 2][1] = t[1];
                bfh[np * 2 + 1][0] = t[2]; bfh[np * 2 + 1][1] = t[3];
                ldsm4(t, bBl + off);
                bfl[np * 2][0] = t[0]; bfl[np * 2][1] = t[1];
                bfl[np * 2 + 1][0] = t[2]; bfl[np * 2 + 1][1] = t[3];
            }
            #pragma unroll
            for (int mt = 0; mt < 2; mt++)
                #pragma unroll
                for (int nt = 0; nt < 8; nt++) {
                    mma16816(c[mt][nt], afh[mt], bfh[nt]);
                    mma16816(c[mt][nt], afh[mt], bfl[nt]);
                    mma16816(c[mt][nt], afl[mt], bfh[nt]);
                }
        }
        __syncthreads();
    }

    // epilogue
    #pragma unroll
    for (int mt = 0; mt < 2; mt++) {
        #pragma unroll
        for (int nt = 0; nt < 8; nt++) {
            int m0 = bm + warp_m * 32 + mt * 16 + (l >> 2);
            int cn = bn + warp_n * 64 + nt * 8 + (l & 3) * 2;
            float2 v0 = make_float2(c[mt][nt][0], c[mt][nt][1]);
            float2 v1 = make_float2(c[mt][nt][2], c[mt][nt][3]);
            *(float2*)&C[(size_t)m0 * GN + cn] = v0;
            *(float2*)&C[(size_t)(m0 + 8) * GN + cn] = v1;
        }
    }
}

// ---------------- fused masked flash attention (unchanged, passing) ----------------
#define ATTN_SMEM_BYTES 87552

__global__ __launch_bounds__(256, 2)
void attn_kernel() {
    extern __shared__ float sm[];
    float* sQ  = sm;                       // 8192
    float* sKT = sm + 8192;                // 8320 (K^T) / reused as sV [64][128]
    float* sS  = sm + 8192 + 8320;         // 4160
    float* gM  = sS + 4160;
    float* gL  = gM + 64;
    float* gSc = gL + 64;
    unsigned char* sMask = (unsigned char*)(gSc + 64);   // 4096 bytes

    int tid = threadIdx.x;
    int qb = blockIdx.x, h = blockIdx.y, b = blockIdx.z;
    int tx = tid & 15, ty = tid >> 4;

    {
        const float* Qg = g_q + ((size_t)(b * Ss + qb * 64)) * HIDD + h * DHh;
        #pragma unroll
        for (int i = 0; i < 8; i++) {
            int vec = tid + i * 256;
            int r = vec >> 5, c4 = (vec & 31) * 4;
            *(float4*)&sQ[r * 128 + c4] = *(const float4*)&Qg[(size_t)r * HIDD + c4];
        }
    }
    if (tid < 64) { gM[tid] = -1e30f; gL[tid] = 0.0f; }

    float o[4][8];
    #pragma unroll
    for (int i = 0; i < 4; i++)
        #pragma unroll
        for (int j = 0; j < 8; j++) o[i][j] = 0.0f;
    __syncthreads();

    for (int kb = 0; kb < NBLK; kb++) {
        if (!g_bany[qb * NBLK + kb]) continue;

        const float* Kg = g_k + ((size_t)(b * Ss + kb * 64)) * HIDD + h * DHh;
        #pragma unroll
        for (int i = 0; i < 8; i++) {
            int vec = tid + i * 256;
            int r = vec >> 5, c4 = (vec & 31) * 4;
            float4 kv = *(const float4*)&Kg[(size_t)r * HIDD + c4];
            sKT[(c4 + 0) * 65 + r] = kv.x;
            sKT[(c4 + 1) * 65 + r] = kv.y;
            sKT[(c4 + 2) * 65 + r] = kv.z;
            sKT[(c4 + 3) * 65 + r] = kv.w;
        }
        {
            const unsigned char* Mg = g_mask + (size_t)(qb * 64) * Ss + kb * 64;
            int r = tid >> 2, off = (tid & 3) * 16;
            *(int4*)&sMask[r * 64 + off] = *(const int4*)&Mg[(size_t)r * Ss + off];
        }
        __syncthreads();

        {
            int sr0 = ty * 4, sc0 = tx * 4;
            float acc[4][4];
            #pragma unroll
            for (int i = 0; i < 4; i++)
                #pragma unroll
                for (int j = 0; j < 4; j++) acc[i][j] = 0.0f;
            #pragma unroll 4
            for (int kk = 0; kk < 128; kk++) {
                float qv[4], kv[4];
                #pragma unroll
                for (int i = 0; i < 4; i++) qv[i] = sQ[(sr0 + i) * 128 + kk];
                #pragma unroll
                for (int j = 0; j < 4; j++) kv[j] = sKT[kk * 65 + sc0 + j];
                #pragma unroll
                for (int i = 0; i < 4; i++)
                    #pragma unroll
                    for (int j = 0; j < 4; j++) acc[i][j] += qv[i] * kv[j];
            }
            #pragma unroll
            for (int i = 0; i < 4; i++)
                #pragma unroll
                for (int j = 0; j < 4; j++) {
                    float v = sMask[(sr0 + i) * 64 + sc0 + j]
                              ? acc[i][j] * SCALE_F : -1e30f;
                    sS[(sr0 + i) * 65 + sc0 + j] = v;
                }
        }
        __syncthreads();

        float* sV = sKT;
        {
            const float* Vg = g_v + ((size_t)(b * Ss + kb * 64)) * HIDD + h * DHh;
            #pragma unroll
            for (int i = 0; i < 8; i++) {
                int vec = tid + i * 256;
                int r = vec >> 5, c4 = (vec & 31) * 4;
                *(float4*)&sV[r * 128 + c4] = *(const float4*)&Vg[(size_t)r * HIDD + c4];
            }
        }
        {
            int row = tid >> 2, seg = tid & 3;
            float* srow = &sS[row * 65 + seg * 16];
            float mx = -1e30f;
            #pragma unroll
            for (int c = 0; c < 16; c++) mx = fmaxf(mx, srow[c]);
            mx = fmaxf(mx, __shfl_xor_sync(0xffffffffu, mx, 1));
            mx = fmaxf(mx, __shfl_xor_sync(0xffffffffu, mx, 2));
            float m_old = gM[row];
            float m_new = fmaxf(m_old, mx);
            float s = 0.0f;
            #pragma unroll
            for (int c = 0; c < 16; c++) {
                float p = __expf(srow[c] - m_new);
                srow[c] = p;
                s += p;
            }
            s += __shfl_xor_sync(0xffffffffu, s, 1);
            s += __shfl_xor_sync(0xffffffffu, s, 2);
            if (seg == 0) {
                float sc = __expf(m_old - m_new);
                gL[row] = gL[row] * sc + s;
                gM[row] = m_new;
                gSc[row] = sc;
            }
        }
        __syncthreads();

        {
            int r0 = ty * 4, c0 = tx * 8;
            #pragma unroll
            for (int i = 0; i < 4; i++) {
                float sc = gSc[r0 + i];
                #pragma unroll
                for (int j = 0; j < 8; j++) o[i][j] *= sc;
            }
            #pragma unroll 2
            for (int kk = 0; kk < 64; kk++) {
                float p[4], vv[8];
                #pragma unroll
                for (int i = 0; i < 4; i++) p[i] = sS[(r0 + i) * 65 + kk];
                *(float4*)&vv[0] = *(float4*)&sV[kk * 128 + c0];
                *(float4*)&vv[4] = *(float4*)&sV[kk * 128 + c0 + 4];
                #pragma unroll
                for (int i = 0; i < 4; i++)
                    #pragma unroll
                    for (int j = 0; j < 8; j++) o[i][j] += p[i] * vv[j];
            }
        }
        __syncthreads();
    }

    {
        int r0 = ty * 4, c0 = tx * 8;
        float* Cg = g_ctx + ((size_t)(b * Ss + qb * 64)) * HIDD + h * DHh;
        #pragma unroll
        for (int i = 0; i < 4; i++) {
            float inv = 1.0f / gL[r0 + i];
            float tmp[8];
            #pragma unroll
            for (int j = 0; j < 8; j++) tmp[j] = o[i][j] * inv;
            *(float4*)&Cg[(size_t)(r0 + i) * HIDD + c0]     = *(float4*)&tmp[0];
            *(float4*)&Cg[(size_t)(r0 + i) * HIDD + c0 + 4] = *(float4*)&tmp[4];
        }
    }
}

// ---------------- launch ----------------
extern "C" void kernel_launch(void* const* d_in, const int* in_sizes, int n_in,
                              void* d_out, int out_size) {
    const float* X  = (const float*)d_in[0];
    const float* Wq = (const float*)d_in[1];
    const float* Wk = (const float*)d_in[2];
    const float* Wv = (const float*)d_in[3];
    const float* Wo = (const float*)d_in[4];
    const void*  Mraw = d_in[5];
    float* out = (float*)d_out;

    cudaFuncSetAttribute(attn_kernel,
                         cudaFuncAttributeMaxDynamicSharedMemorySize, ATTN_SMEM_BYTES);
    cudaFuncSetAttribute(gemm_hmma_x3,
                         cudaFuncAttributeMaxDynamicSharedMemorySize, GSMEM_TOTAL);

    // mask canonicalization
    detect_kernel<<<1, 1>>>((const unsigned char*)Mraw);
    expand_kernel<<<(Ss * Ss) / 256, 256>>>(Mraw);
    bany_kernel<<<dim3(NBLK, NBLK), 64>>>();

    // scratch pointers
    float *pq, *pk, *pv, *pctx;
    __nv_bfloat16 *pxhi, *pxlo, *pchi, *pclo, *pwhi, *pwlo;
    cudaGetSymbolAddress((void**)&pq,   g_q);
    cudaGetSymbolAddress((void**)&pk,   g_k);
    cudaGetSymbolAddress((void**)&pv,   g_v);
    cudaGetSymbolAddress((void**)&pctx, g_ctx);
    cudaGetSymbolAddress((void**)&pxhi, g_xhi);
    cudaGetSymbolAddress((void**)&pxlo, g_xlo);
    cudaGetSymbolAddress((void**)&pchi, g_chi);
    cudaGetSymbolAddress((void**)&pclo, g_clo);
    cudaGetSymbolAddress((void**)&pwhi, g_wthi);
    cudaGetSymbolAddress((void**)&pwlo, g_wtlo);

    const size_t WSZ = (size_t)HIDD * HIDD;

    // operand preparation
    split_kernel<<<(MROWS * HIDD / 4 + 255) / 256, 256>>>(X, pxhi, pxlo, MROWS * HIDD / 4);
    dim3 tgrid(HIDD / 32, HIDD / 32);
    tsplit_kernel<<<tgrid, dim3(32, 8)>>>(Wq, pwhi + 0 * WSZ, pwlo + 0 * WSZ);
    tsplit_kernel<<<tgrid, dim3(32, 8)>>>(Wk, pwhi + 1 * WSZ, pwlo + 1 * WSZ);
    tsplit_kernel<<<tgrid, dim3(32, 8)>>>(Wv, pwhi + 2 * WSZ, pwlo + 2 * WSZ);
    tsplit_kernel<<<tgrid, dim3(32, 8)>>>(Wo, pwhi + 3 * WSZ, pwlo + 3 * WSZ);

    // projections (HMMA bf16x3)
    dim3 ggrid(GN / 128, MROWS / 128);   // (16, 32)
    gemm_hmma_x3<<<ggrid, 256, GSMEM_TOTAL>>>(pxhi, pxlo, pwhi + 0 * WSZ, pwlo + 0 * WSZ, pq);
    gemm_hmma_x3<<<ggrid, 256, GSMEM_TOTAL>>>(pxhi, pxlo, pwhi + 1 * WSZ, pwlo + 1 * WSZ, pk);
    gemm_hmma_x3<<<ggrid, 256, GSMEM_TOTAL>>>(pxhi, pxlo, pwhi + 2 * WSZ, pwlo + 2 * WSZ, pv);

    // attention
    attn_kernel<<<dim3(Ss / 64, Hh, Bb), 256, ATTN_SMEM_BYTES>>>();

    // output projection
    split_kernel<<<(MROWS * HIDD / 4 + 255) / 256, 256>>>(pctx, pchi, pclo, MROWS * HIDD / 4);
    gemm_hmma_x3<<<ggrid, 256, GSMEM_TOTAL>>>(pchi, pclo, pwhi + 3 * WSZ, pwlo + 3 * WSZ, out);
}

// round 5
// speedup vs baseline: 3.1454x; 1.4965x over previous
#include <cuda_runtime.h>
#include <cuda_bf16.h>
#include <stdint.h>
#include <math.h>

// Problem constants
#define Bb    2
#define Ss    2048
#define HIDD  2048
#define Hh    16
#define DHh   128
#define NBLK  32        // 2048 / 64
#define MROWS 4096      // B*S
#define SCALE_F 0.08838834764831845f   // 1/sqrt(128)

// ---------------- scratch (static device allocations) ----------------
__device__ float g_v[(size_t)MROWS * HIDD];
__device__ __nv_bfloat16 g_xhi[(size_t)MROWS * HIDD];
__device__ __nv_bfloat16 g_xlo[(size_t)MROWS * HIDD];
__device__ __nv_bfloat16 g_qhi[(size_t)MROWS * HIDD];
__device__ __nv_bfloat16 g_qlo[(size_t)MROWS * HIDD];
__device__ __nv_bfloat16 g_khi[(size_t)MROWS * HIDD];
__device__ __nv_bfloat16 g_klo[(size_t)MROWS * HIDD];
__device__ __nv_bfloat16 g_vthi[(size_t)MROWS * HIDD];   // [b][h*dh][s]
__device__ __nv_bfloat16 g_vtlo[(size_t)MROWS * HIDD];
__device__ __nv_bfloat16 g_chi[(size_t)MROWS * HIDD];
__device__ __nv_bfloat16 g_clo[(size_t)MROWS * HIDD];
__device__ __nv_bfloat16 g_wthi[4][(size_t)HIDD * HIDD];   // W^T [N][K] hi
__device__ __nv_bfloat16 g_wtlo[4][(size_t)HIDD * HIDD];   // W^T [N][K] lo
__device__ unsigned char g_mask[(size_t)Ss * Ss];
__device__ unsigned char g_bany[NBLK * NBLK];
__device__ int g_flag;

// ======================= PTX helpers (family-portable) =======================
__device__ __forceinline__ uint32_t smem_u32(const void* p) {
    uint32_t a;
    asm("{ .reg .u64 t; cvta.to.shared.u64 t, %1; cvt.u32.u64 %0, t; }"
        : "=r"(a) : "l"(p));
    return a;
}
__device__ __forceinline__ void cp_async16(uint32_t dst, const void* src) {
    asm volatile("cp.async.cg.shared.global [%0], [%1], 16;"
                 :: "r"(dst), "l"(src) : "memory");
}
#define CP_COMMIT() asm volatile("cp.async.commit_group;" ::: "memory")
#define CP_WAIT(n)  asm volatile("cp.async.wait_group %0;" :: "n"(n) : "memory")

__device__ __forceinline__ void ldsm4(uint32_t* r, uint32_t addr) {
    asm volatile("ldmatrix.sync.aligned.m8n8.x4.shared.b16 {%0,%1,%2,%3}, [%4];"
                 : "=r"(r[0]), "=r"(r[1]), "=r"(r[2]), "=r"(r[3]) : "r"(addr));
}
__device__ __forceinline__ void mma16816(float* c, const uint32_t* a, const uint32_t* b) {
    asm volatile(
        "mma.sync.aligned.m16n8k16.row.col.f32.bf16.bf16.f32 "
        "{%0,%1,%2,%3}, {%4,%5,%6,%7}, {%8,%9}, {%0,%1,%2,%3};"
        : "+f"(c[0]), "+f"(c[1]), "+f"(c[2]), "+f"(c[3])
        : "r"(a[0]), "r"(a[1]), "r"(a[2]), "r"(a[3]), "r"(b[0]), "r"(b[1]));
}

#define SW128(o) ((o) ^ (((o) >> 3) & 0x70))

__device__ __forceinline__ uint32_t pack_bf16(float a, float b) {
    __nv_bfloat162 t = __floats2bfloat162_rn(a, b);
    return *(uint32_t*)&t;
}

// ---------------- mask dtype detection + canonicalization ----------------
__global__ void detect_kernel(const unsigned char* __restrict__ raw) {
    int f;
    if (raw[0] == 1 && raw[1] == 1) f = 0;       // u8 / bool
    else if (raw[0] == 1)           f = 1;       // int32
    else                            f = 2;       // float32
    g_flag = f;
}

__global__ void expand_kernel(const void* __restrict__ raw) {
    size_t idx = (size_t)blockIdx.x * blockDim.x + threadIdx.x;
    if (idx >= (size_t)Ss * Ss) return;
    int f = g_flag;
    unsigned char v;
    if (f == 0)      v = ((const unsigned char*)raw)[idx] != 0;
    else if (f == 1) v = ((const int*)raw)[idx] != 0;
    else             v = ((const float*)raw)[idx] != 0.0f;
    g_mask[idx] = v;
}

__global__ void bany_kernel() {
    int qb = blockIdx.y, kb = blockIdx.x;
    int r = threadIdx.x;   // 64 threads
    const unsigned char* row = &g_mask[(size_t)(qb * 64 + r) * Ss + kb * 64];
    int any = 0;
    #pragma unroll 8
    for (int c = 0; c < 64; c++) any |= row[c];
    int res = __syncthreads_or(any);
    if (r == 0) g_bany[qb * NBLK + kb] = res ? 1 : 0;
}

// ---------------- fp32 -> bf16 hi/lo split ----------------
__global__ void split_kernel(const float* __restrict__ in,
                             __nv_bfloat16* __restrict__ hi,
                             __nv_bfloat16* __restrict__ lo, int n4) {
    int i = blockIdx.x * blockDim.x + threadIdx.x;
    if (i >= n4) return;
    float4 v = ((const float4*)in)[i];
    __nv_bfloat16 h0 = __float2bfloat16(v.x), h1 = __float2bfloat16(v.y);
    __nv_bfloat16 h2 = __float2bfloat16(v.z), h3 = __float2bfloat16(v.w);
    __nv_bfloat16 l0 = __float2bfloat16(v.x - __bfloat162float(h0));
    __nv_bfloat16 l1 = __float2bfloat16(v.y - __bfloat162float(h1));
    __nv_bfloat16 l2 = __float2bfloat16(v.z - __bfloat162float(h2));
    __nv_bfloat16 l3 = __float2bfloat16(v.w - __bfloat162float(h3));
    ushort4 hv = make_ushort4(__bfloat16_as_ushort(h0), __bfloat16_as_ushort(h1),
                              __bfloat16_as_ushort(h2), __bfloat16_as_ushort(h3));
    ushort4 lv = make_ushort4(__bfloat16_as_ushort(l0), __bfloat16_as_ushort(l1),
                              __bfloat16_as_ushort(l2), __bfloat16_as_ushort(l3));
    ((ushort4*)hi)[i] = hv;
    ((ushort4*)lo)[i] = lv;
}

// ---------------- transpose + split: W[K][N] -> T[N][K] hi/lo ----------------
__global__ void tsplit_kernel(const float* __restrict__ W,
                              __nv_bfloat16* __restrict__ Thi,
                              __nv_bfloat16* __restrict__ Tlo) {
    __shared__ float t[32][33];
    int n0 = blockIdx.x * 32, k0 = blockIdx.y * 32;
    int tx = threadIdx.x, ty = threadIdx.y;   // block (32, 8)
    #pragma unroll
    for (int i = 0; i < 4; i++)
        t[ty + i * 8][tx] = W[(size_t)(k0 + ty + i * 8) * HIDD + n0 + tx];
    __syncthreads();
    #pragma unroll
    for (int i = 0; i < 4; i++) {
        float x = t[tx][ty + i * 8];
        __nv_bfloat16 h = __float2bfloat16(x);
        __nv_bfloat16 l = __float2bfloat16(x - __bfloat162float(h));
        size_t o = (size_t)(n0 + ty + i * 8) * HIDD + k0 + tx;
        Thi[o] = h;
        Tlo[o] = l;
    }
}

// ---------------- transpose + split V: g_v[m][n] -> vt[(b*2048+n)][s] hi/lo ----
__global__ void vtsplit_kernel(__nv_bfloat16* __restrict__ Thi,
                               __nv_bfloat16* __restrict__ Tlo) {
    __shared__ float t[32][33];
    int n0 = blockIdx.x * 32, m0 = blockIdx.y * 32;
    int tx = threadIdx.x, ty = threadIdx.y;   // block (32, 8)
    #pragma unroll
    for (int i = 0; i < 4; i++)
        t[ty + i * 8][tx] = g_v[(size_t)(m0 + ty + i * 8) * HIDD + n0 + tx];
    __syncthreads();
    int b = m0 >> 11;
    int s0 = m0 & 2047;
    #pragma unroll
    for (int i = 0; i < 4; i++) {
        float x = t[tx][ty + i * 8];
        __nv_bfloat16 h = __float2bfloat16(x);
        __nv_bfloat16 l = __float2bfloat16(x - __bfloat162float(h));
        size_t o = ((size_t)b * 2048 + n0 + ty + i * 8) * 2048 + s0 + tx;
        Thi[o] = h;
        Tlo[o] = l;
    }
}

// ---------------- HMMA bf16x3 GEMM ----------------
// C = A @ B^T;  A [M][K] split hi/lo, B [N][K] K-major split hi/lo.
// Epilogue: fp32 C (if Chi==null) or bf16 hi/lo pair (Chi/Clo).
#define GK 2048
#define GN 2048
#define NIT 32
#define GTILE_BYTES 16384
#define GSTAGE (4 * GTILE_BYTES)
#define GSMEM_TOTAL (2 * GSTAGE)

__global__ __launch_bounds__(256, 1)
void gemm_hmma_x3(const __nv_bfloat16* __restrict__ Ahi,
                  const __nv_bfloat16* __restrict__ Alo,
                  const __nv_bfloat16* __restrict__ Bhi,
                  const __nv_bfloat16* __restrict__ Blo,
                  float* __restrict__ C,
                  __nv_bfloat16* __restrict__ Chi,
                  __nv_bfloat16* __restrict__ Clo) {
    extern __shared__ char smem[];
    uint32_t sb = smem_u32(smem);
    int tid = threadIdx.x, l = tid & 31, wid = tid >> 5;
    int warp_m = wid & 3, warp_n = wid >> 2;
    int bm = blockIdx.y * 128, bn = blockIdx.x * 128;

    const char* src[4] = {
        (const char*)(Ahi + (size_t)bm * GK),
        (const char*)(Alo + (size_t)bm * GK),
        (const char*)(Bhi + (size_t)bn * GK),
        (const char*)(Blo + (size_t)bn * GK)
    };

    float c[2][8][4];
    #pragma unroll
    for (int i = 0; i < 2; i++)
        #pragma unroll
        for (int j = 0; j < 8; j++)
            #pragma unroll
            for (int k = 0; k < 4; k++) c[i][j][k] = 0.0f;

    int srow[4], scol[4];
    #pragma unroll
    for (int j = 0; j < 4; j++) {
        int v = tid + j * 256;
        srow[j] = v >> 3;
        scol[j] = (v & 7) * 16;
    }

    auto stage_load = [&](int ci, int st) {
        int koff = ci * 128;
        #pragma unroll
        for (int w = 0; w < 4; w++) {
            uint32_t dst = sb + st * GSTAGE + w * GTILE_BYTES;
            const char* s = src[w] + koff;
            #pragma unroll
            for (int j = 0; j < 4; j++) {
                cp_async16(dst + SW128(srow[j] * 128 + scol[j]),
                           s + (size_t)srow[j] * (GK * 2) + scol[j]);
            }
        }
    };

    int rrA = (l & 7) + ((l >> 3) & 1) * 8;
    int kbA = ((l >> 4) & 1) * 16;
    int rrB = (l & 7) + ((l >> 4) & 1) * 8;
    int kbB = ((l >> 3) & 1) * 16;

    stage_load(0, 0);
    CP_COMMIT();

    for (int i = 0; i < NIT; i++) {
        if (i + 1 < NIT) {
            stage_load(i + 1, (i + 1) & 1);
            CP_COMMIT();
            CP_WAIT(1);
        } else {
            CP_WAIT(0);
        }
        __syncthreads();

        uint32_t bAh = sb + (i & 1) * GSTAGE;
        uint32_t bAl = bAh + GTILE_BYTES;
        uint32_t bBh = bAh + 2 * GTILE_BYTES;
        uint32_t bBl = bAh + 3 * GTILE_BYTES;

        #pragma unroll
        for (int ks = 0; ks < 4; ks++) {
            int kk = ks * 32;
            uint32_t afh[2][4], afl[2][4];
            #pragma unroll
            for (int mt = 0; mt < 2; mt++) {
                int rb = (warp_m * 32 + mt * 16 + rrA) * 128;
                uint32_t off = rb + ((kk + kbA) ^ ((rb >> 3) & 0x70));
                ldsm4(afh[mt], bAh + off);
                ldsm4(afl[mt], bAl + off);
            }
            uint32_t bfh[8][2], bfl[8][2];
            #pragma unroll
            for (int np = 0; np < 4; np++) {
                int rb = (warp_n * 64 + np * 16 + rrB) * 128;
                uint32_t off = rb + ((kk + kbB) ^ ((rb >> 3) & 0x70));
                uint32_t t[4];
                ldsm4(t, bBh + off);
                bfh[np * 2][0] = t[0]; bfh[np * 2][1] = t[1];
                bfh[np * 2 + 1][0] = t[2]; bfh[np * 2 + 1][1] = t[3];
                ldsm4(t, bBl + off);
                bfl[np * 2][0] = t[0]; bfl[np * 2][1] = t[1];
                bfl[np * 2 + 1][0] = t[2]; bfl[np * 2 + 1][1] = t[3];
            }
            #pragma unroll
            for (int mt = 0; mt < 2; mt++)
                #pragma unroll
                for (int nt = 0; nt < 8; nt++) {
                    mma16816(c[mt][nt], afh[mt], bfh[nt]);
                    mma16816(c[mt][nt], afh[mt], bfl[nt]);
                    mma16816(c[mt][nt], afl[mt], bfh[nt]);
                }
        }
        __syncthreads();
    }

    // epilogue
    #pragma unroll
    for (int mt = 0; mt < 2; mt++) {
        #pragma unroll
        for (int nt = 0; nt < 8; nt++) {
            int m0 = bm + warp_m * 32 + mt * 16 + (l >> 2);
            int cn = bn + warp_n * 64 + nt * 8 + (l & 3) * 2;
            if (Chi) {
                float v0 = c[mt][nt][0], v1 = c[mt][nt][1];
                float v2 = c[mt][nt][2], v3 = c[mt][nt][3];
                __nv_bfloat16 h0 = __float2bfloat16(v0), h1 = __float2bfloat16(v1);
                __nv_bfloat16 h2 = __float2bfloat16(v2), h3 = __float2bfloat16(v3);
                size_t i0 = (size_t)m0 * GN + cn, i1 = (size_t)(m0 + 8) * GN + cn;
                *(uint32_t*)&Chi[i0] = pack_bf16(__bfloat162float(h0), __bfloat162float(h1));
                *(uint32_t*)&Chi[i1] = pack_bf16(__bfloat162float(h2), __bfloat162float(h3));
                *(uint32_t*)&Clo[i0] = pack_bf16(v0 - __bfloat162float(h0), v1 - __bfloat162float(h1));
                *(uint32_t*)&Clo[i1] = pack_bf16(v2 - __bfloat162float(h2), v3 - __bfloat162float(h3));
            } else {
                float2 v0 = make_float2(c[mt][nt][0], c[mt][nt][1]);
                float2 v1 = make_float2(c[mt][nt][2], c[mt][nt][3]);
                *(float2*)&C[(size_t)m0 * GN + cn] = v0;
                *(float2*)&C[(size_t)(m0 + 8) * GN + cn] = v1;
            }
        }
    }
}

// ---------------- HMMA bf16x3 flash attention ----------------
// grid (qb=32, h=16, b=2), 128 threads (4 warps). Warp w owns q rows [w*16, w*16+16).
#define A_SQ       0                       // Q: hi c0, hi c1, lo c0, lo c1 (4 x 8KB)
#define A_KV(st)   (32768 + (st) * 65536)  // Khi c0/c1, Klo c0/c1 (32KB), VThi (16KB), VTlo (16KB)
#define A_P        163840                  // Phi 8KB, Plo 8KB
#define A_MASK(st) (180224 + (st) * 4096)
#define A_LIST     188416                  // int count + int[32]
#define ATTN2_SMEM 188672

__global__ __launch_bounds__(128, 1)
void attn_mma() {
    extern __shared__ char sm[];
    uint32_t sb = smem_u32(sm);
    int tid = threadIdx.x, l = tid & 31, w = tid >> 5;
    int qb = blockIdx.x, h = blockIdx.y, b = blockIdx.z;

    int rrA = (l & 7) + ((l >> 3) & 1) * 8;
    int kbA = ((l >> 4) & 1) * 16;
    int rrB = (l & 7) + ((l >> 4) & 1) * 8;
    int kbB = ((l >> 3) & 1) * 16;

    const size_t qrow_base = ((size_t)b * Ss + qb * 64) * HIDD;   // elements
    const size_t colb_base = (size_t)h * 256;                     // bytes within row

    // ---- load Q tiles (hi c0, hi c1, lo c0, lo c1) ----
    {
        #pragma unroll
        for (int t = 0; t < 4; t++) {
            const char* base = (const char*)((t < 2) ? g_qhi : g_qlo) + qrow_base * 2
                               + colb_base + (t & 1) * 128;
            uint32_t dst = sb + A_SQ + t * 8192;
            #pragma unroll
            for (int j = 0; j < 4; j++) {
                int vec = tid + j * 128;
                int row = vec >> 3, cbt = (vec & 7) * 16;
                cp_async16(dst + SW128(row * 128 + cbt),
                           base + (size_t)row * 4096 + cbt);
            }
        }
        CP_COMMIT();
    }

    // ---- build visible-kb list ----
    int* sList = (int*)(sm + A_LIST);
    if (tid == 0) {
        int c = 0;
        for (int kb = 0; kb < NBLK; kb++)
            if (g_bany[qb * NBLK + kb]) sList[1 + c++] = kb;
        sList[0] = c;
    }
    __syncthreads();
    int cnt = sList[0];

    // ---- KV + mask prefetch ----
    auto prefetch = [&](int kb, int st) {
        uint32_t kvb = sb + A_KV(st);
        size_t krow = ((size_t)b * Ss + kb * 64) * HIDD * 2;   // bytes
        #pragma unroll
        for (int t = 0; t < 4; t++) {
            const char* base = (const char*)((t < 2) ? g_khi : g_klo) + krow
                               + colb_base + (t & 1) * 128;
            uint32_t dst = kvb + t * 8192;
            #pragma unroll
            for (int j = 0; j < 4; j++) {
                int vec = tid + j * 128;
                int row = vec >> 3, cbt = (vec & 7) * 16;
                cp_async16(dst + SW128(row * 128 + cbt),
                           base + (size_t)row * 4096 + cbt);
            }
        }
        size_t vrow = ((size_t)b * 2048 + h * 128) * 2048 * 2;  // bytes; +dh*4096
        #pragma unroll
        for (int t = 0; t < 2; t++) {
            const char* base = (const char*)(t == 0 ? g_vthi : g_vtlo) + vrow + kb * 128;
            uint32_t dst = kvb + 32768 + t * 16384;
            #pragma unroll
            for (int j = 0; j < 8; j++) {
                int vec = tid + j * 128;
                int row = vec >> 3, cbt = (vec & 7) * 16;
                cp_async16(dst + SW128(row * 128 + cbt),
                           base + (size_t)row * 4096 + cbt);
            }
        }
        {
            const char* base = (const char*)g_mask + (size_t)(qb * 64) * Ss + kb * 64;
            uint32_t dst = sb + A_MASK(st);
            #pragma unroll
            for (int j = 0; j < 2; j++) {
                int vec = tid + j * 128;
                int row = vec >> 2, cbt = (vec & 3) * 16;
                cp_async16(dst + row * 64 + cbt, base + (size_t)row * Ss + cbt);
            }
        }
    };

    prefetch(sList[1], 0);
    CP_COMMIT();

    // ---- state ----
    float o[16][4];
    #pragma unroll
    for (int i = 0; i < 16; i++)
        #pragma unroll
        for (int j = 0; j < 4; j++) o[i][j] = 0.0f;
    float m0r = -1e30f, m1r = -1e30f, l0r = 0.0f, l1r = 0.0f;

    int qrow0 = w * 16;
    int r0l = qrow0 + (l >> 2);

    for (int i = 0; i < cnt; i++) {
        int st = i & 1;
        __syncthreads();   // all warps done with stage st^1 (iter i-1) before refill
        if (i + 1 < cnt) {
            prefetch(sList[1 + i + 1], st ^ 1);
            CP_COMMIT();
            CP_WAIT(1);
        } else {
            CP_WAIT(0);
        }
        __syncthreads();

        uint32_t kvb = sb + A_KV(st);

        // ---- S = Q @ K^T (bf16x3) ----
        float s[8][4];
        #pragma unroll
        for (int nt = 0; nt < 8; nt++)
            #pragma unroll
            for (int j = 0; j < 4; j++) s[nt][j] = 0.0f;

        #pragma unroll
        for (int chunk = 0; chunk < 2; chunk++) {
            uint32_t bQh = sb + A_SQ + chunk * 8192;
            uint32_t bQl = sb + A_SQ + 16384 + chunk * 8192;
            uint32_t bKh = kvb + chunk * 8192;
            uint32_t bKl = kvb + 16384 + chunk * 8192;
            #pragma unroll
            for (int ks = 0; ks < 4; ks++) {
                int kk = ks * 32;
                int rowA = qrow0 + rrA;
                uint32_t offA = rowA * 128 + ((kk + kbA) ^ ((rowA & 7) << 4));
                uint32_t ah[4], al[4];
                ldsm4(ah, bQh + offA);
                ldsm4(al, bQl + offA);
                #pragma unroll
                for (int np = 0; np < 4; np++) {
                    int rowB = np * 16 + rrB;
                    uint32_t offB = rowB * 128 + ((kk + kbB) ^ ((rowB & 7) << 4));
                    uint32_t th[4], tl[4];
                    ldsm4(th, bKh + offB);
                    ldsm4(tl, bKl + offB);
                    uint32_t bh0[2] = {th[0], th[1]}, bh1[2] = {th[2], th[3]};
                    uint32_t bl0[2] = {tl[0], tl[1]}, bl1[2] = {tl[2], tl[3]};
                    mma16816(s[np * 2], ah, bh0);
                    mma16816(s[np * 2], ah, bl0);
                    mma16816(s[np * 2], al, bh0);
                    mma16816(s[np * 2 + 1], ah, bh1);
                    mma16816(s[np * 2 + 1], ah, bl1);
                    mma16816(s[np * 2 + 1], al, bh1);
                }
            }
        }

        // ---- mask + scale + online softmax ----
        const unsigned char* mk = (const unsigned char*)(sm + A_MASK(st))
                                  + r0l * 64 + (l & 3) * 2;
        float mx0 = -1e30f, mx1 = -1e30f;
        #pragma unroll
        for (int nt = 0; nt < 8; nt++) {
            int cb = nt * 8;
            float t00 = mk[cb]       ? s[nt][0] * SCALE_F : -1e30f;
            float t01 = mk[cb + 1]   ? s[nt][1] * SCALE_F : -1e30f;
            float t10 = mk[cb + 512] ? s[nt][2] * SCALE_F : -1e30f;
            float t11 = mk[cb + 513] ? s[nt][3] * SCALE_F : -1e30f;
            s[nt][0] = t00; s[nt][1] = t01; s[nt][2] = t10; s[nt][3] = t11;
            mx0 = fmaxf(mx0, fmaxf(t00, t01));
            mx1 = fmaxf(mx1, fmaxf(t10, t11));
        }
        mx0 = fmaxf(mx0, __shfl_xor_sync(0xffffffffu, mx0, 1));
        mx0 = fmaxf(mx0, __shfl_xor_sync(0xffffffffu, mx0, 2));
        mx1 = fmaxf(mx1, __shfl_xor_sync(0xffffffffu, mx1, 1));
        mx1 = fmaxf(mx1, __shfl_xor_sync(0xffffffffu, mx1, 2));
        float mn0 = fmaxf(m0r, mx0), mn1 = fmaxf(m1r, mx1);
        float sc0 = __expf(m0r - mn0), sc1 = __expf(m1r - mn1);
        m0r = mn0; m1r = mn1;

        // ---- P = exp(S - m), write hi/lo to smem with FULL-column swizzle ----
        float sum0 = 0.0f, sum1 = 0.0f;
        int colb = (l & 3) * 4;
        int sw0 = (r0l & 7) << 4;                 // same for r0l and r0l+8
        uint32_t rb0 = r0l * 128;
        uint32_t rb1 = (r0l + 8) * 128;
        #pragma unroll
        for (int nt = 0; nt < 8; nt++) {
            float p00 = __expf(s[nt][0] - mn0);
            float p01 = __expf(s[nt][1] - mn0);
            float p10 = __expf(s[nt][2] - mn1);
            float p11 = __expf(s[nt][3] - mn1);
            sum0 += p00 + p01;
            sum1 += p10 + p11;
            __nv_bfloat16 h00 = __float2bfloat16(p00), h01 = __float2bfloat16(p01);
            __nv_bfloat16 h10 = __float2bfloat16(p10), h11 = __float2bfloat16(p11);
            uint32_t colsw = (uint32_t)((nt * 16 + colb) ^ sw0);
            uint32_t a0 = rb0 + colsw;
            uint32_t a1 = rb1 + colsw;
            *(uint32_t*)(sm + A_P + a0) =
                pack_bf16(__bfloat162float(h00), __bfloat162float(h01));
            *(uint32_t*)(sm + A_P + a1) =
                pack_bf16(__bfloat162float(h10), __bfloat162float(h11));
            *(uint32_t*)(sm + A_P + 8192 + a0) =
                pack_bf16(p00 - __bfloat162float(h00), p01 - __bfloat162float(h01));
            *(uint32_t*)(sm + A_P + 8192 + a1) =
                pack_bf16(p10 - __bfloat162float(h10), p11 - __bfloat162float(h11));
        }
        sum0 += __shfl_xor_sync(0xffffffffu, sum0, 1);
        sum0 += __shfl_xor_sync(0xffffffffu, sum0, 2);
        sum1 += __shfl_xor_sync(0xffffffffu, sum1, 1);
        sum1 += __shfl_xor_sync(0xffffffffu, sum1, 2);
        l0r = l0r * sc0 + sum0;
        l1r = l1r * sc1 + sum1;

        // ---- O rescale + O += P @ Vt (bf16x3) ----
        #pragma unroll
        for (int nt = 0; nt < 16; nt++) {
            o[nt][0] *= sc0; o[nt][1] *= sc0;
            o[nt][2] *= sc1; o[nt][3] *= sc1;
        }
        __syncwarp();

        uint32_t bPh = sb + A_P, bPl = sb + A_P + 8192;
        uint32_t bVh = kvb + 32768, bVl = kvb + 49152;
        #pragma unroll
        for (int ks = 0; ks < 4; ks++) {
            int kk = ks * 32;
            int rowA = qrow0 + rrA;
            uint32_t offA = rowA * 128 + ((kk + kbA) ^ ((rowA & 7) << 4));
            uint32_t ph[4], pl[4];
            ldsm4(ph, bPh + offA);
            ldsm4(pl, bPl + offA);
            #pragma unroll
            for (int np = 0; np < 8; np++) {
                int rowB = np * 16 + rrB;
                uint32_t offB = rowB * 128 + ((kk + kbB) ^ ((rowB & 7) << 4));
                uint32_t th[4], tl[4];
                ldsm4(th, bVh + offB);
                ldsm4(tl, bVl + offB);
                uint32_t vh0[2] = {th[0], th[1]}, vh1[2] = {th[2], th[3]};
                uint32_t vl0[2] = {tl[0], tl[1]}, vl1[2] = {tl[2], tl[3]};
                mma16816(o[np * 2], ph, vh0);
                mma16816(o[np * 2], pl, vh0);
                mma16816(o[np * 2], ph, vl0);
                mma16816(o[np * 2 + 1], ph, vh1);
                mma16816(o[np * 2 + 1], pl, vh1);
                mma16816(o[np * 2 + 1], ph, vl1);
            }
        }
    }

    // ---- epilogue: O /= l, write ctx hi/lo bf16 ----
    float inv0 = 1.0f / l0r, inv1 = 1.0f / l1r;
    size_t row0 = (size_t)b * Ss + qb * 64 + qrow0 + (l >> 2);
    size_t row1 = row0 + 8;
    int cn0 = h * 128 + (l & 3) * 2;
    #pragma unroll
    for (int nt = 0; nt < 16; nt++) {
        int cn = cn0 + nt * 8;
        float v0 = o[nt][0] * inv0, v1 = o[nt][1] * inv0;
        float v2 = o[nt][2] * inv1, v3 = o[nt][3] * inv1;
        __nv_bfloat16 h0 = __float2bfloat16(v0), h1 = __float2bfloat16(v1);
        __nv_bfloat16 h2 = __float2bfloat16(v2), h3 = __float2bfloat16(v3);
        size_t i0 = row0 * HIDD + cn, i1 = row1 * HIDD + cn;
        *(uint32_t*)&g_chi[i0] = pack_bf16(__bfloat162float(h0), __bfloat162float(h1));
        *(uint32_t*)&g_chi[i1] = pack_bf16(__bfloat162float(h2), __bfloat162float(h3));
        *(uint32_t*)&g_clo[i0] = pack_bf16(v0 - __bfloat162float(h0), v1 - __bfloat162float(h1));
        *(uint32_t*)&g_clo[i1] = pack_bf16(v2 - __bfloat162float(h2), v3 - __bfloat162float(h3));
    }
}

// ---------------- launch ----------------
extern "C" void kernel_launch(void* const* d_in, const int* in_sizes, int n_in,
                              void* d_out, int out_size) {
    const float* X  = (const float*)d_in[0];
    const float* Wq = (const float*)d_in[1];
    const float* Wk = (const float*)d_in[2];
    const float* Wv = (const float*)d_in[3];
    const float* Wo = (const float*)d_in[4];
    const void*  Mraw = d_in[5];
    float* out = (float*)d_out;

    cudaFuncSetAttribute(gemm_hmma_x3,
                         cudaFuncAttributeMaxDynamicSharedMemorySize, GSMEM_TOTAL);
    cudaFuncSetAttribute(attn_mma,
                         cudaFuncAttributeMaxDynamicSharedMemorySize, ATTN2_SMEM);

    // mask canonicalization
    detect_kernel<<<1, 1>>>((const unsigned char*)Mraw);
    expand_kernel<<<(Ss * Ss) / 256, 256>>>(Mraw);
    bany_kernel<<<dim3(NBLK, NBLK), 64>>>();

    // scratch pointers
    float* pv;
    __nv_bfloat16 *pxhi, *pxlo, *pqhi, *pqlo, *pkhi, *pklo, *pvthi, *pvtlo,
                  *pchi, *pclo, *pwhi, *pwlo;
    cudaGetSymbolAddress((void**)&pv,    g_v);
    cudaGetSymbolAddress((void**)&pxhi,  g_xhi);
    cudaGetSymbolAddress((void**)&pxlo,  g_xlo);
    cudaGetSymbolAddress((void**)&pqhi,  g_qhi);
    cudaGetSymbolAddress((void**)&pqlo,  g_qlo);
    cudaGetSymbolAddress((void**)&pkhi,  g_khi);
    cudaGetSymbolAddress((void**)&pklo,  g_klo);
    cudaGetSymbolAddress((void**)&pvthi, g_vthi);
    cudaGetSymbolAddress((void**)&pvtlo, g_vtlo);
    cudaGetSymbolAddress((void**)&pchi,  g_chi);
    cudaGetSymbolAddress((void**)&pclo,  g_clo);
    cudaGetSymbolAddress((void**)&pwhi,  g_wthi);
    cudaGetSymbolAddress((void**)&pwlo,  g_wtlo);

    const size_t WSZ = (size_t)HIDD * HIDD;

    // operand preparation
    split_kernel<<<(MROWS * HIDD / 4 + 255) / 256, 256>>>(X, pxhi, pxlo, MROWS * HIDD / 4);
    dim3 tgrid(HIDD / 32, HIDD / 32);
    tsplit_kernel<<<tgrid, dim3(32, 8)>>>(Wq, pwhi + 0 * WSZ, pwlo + 0 * WSZ);
    tsplit_kernel<<<tgrid, dim3(32, 8)>>>(Wk, pwhi + 1 * WSZ, pwlo + 1 * WSZ);
    tsplit_kernel<<<tgrid, dim3(32, 8)>>>(Wv, pwhi + 2 * WSZ, pwlo + 2 * WSZ);
    tsplit_kernel<<<tgrid, dim3(32, 8)>>>(Wo, pwhi + 3 * WSZ, pwlo + 3 * WSZ);

    // projections
    dim3 ggrid(GN / 128, MROWS / 128);
    gemm_hmma_x3<<<ggrid, 256, GSMEM_TOTAL>>>(pxhi, pxlo, pwhi + 0 * WSZ, pwlo + 0 * WSZ,
                                              nullptr, pqhi, pqlo);
    gemm_hmma_x3<<<ggrid, 256, GSMEM_TOTAL>>>(pxhi, pxlo, pwhi + 1 * WSZ, pwlo + 1 * WSZ,
                                              nullptr, pkhi, pklo);
    gemm_hmma_x3<<<ggrid, 256, GSMEM_TOTAL>>>(pxhi, pxlo, pwhi + 2 * WSZ, pwlo + 2 * WSZ,
                                              pv, nullptr, nullptr);
    vtsplit_kernel<<<dim3(HIDD / 32, MROWS / 32), dim3(32, 8)>>>(pvthi, pvtlo);

    // attention (HMMA)
    attn_mma<<<dim3(NBLK, Hh, Bb), 128, ATTN2_SMEM>>>();

    // output projection
    gemm_hmma_x3<<<ggrid, 256, GSMEM_TOTAL>>>(pchi, pclo, pwhi + 3 * WSZ, pwlo + 3 * WSZ,
                                              out, nullptr, nullptr);
}

// round 6
// speedup vs baseline: 4.4127x; 1.4029x over previous
#include <cuda_runtime.h>
#include <cuda_fp16.h>
#include <stdint.h>
#include <math.h>

// Problem constants
#define Bb    2
#define Ss    2048
#define HIDD  2048
#define Hh    16
#define DHh   128
#define NBLK  32        // 2048 / 64
#define MROWS 4096      // B*S
#define SCALE_F 0.08838834764831845f   // 1/sqrt(128)

// ---------------- scratch (static device allocations) ----------------
__device__ float g_v[(size_t)MROWS * HIDD];
__device__ __half g_xhi[(size_t)MROWS * HIDD];
__device__ __half g_xlo[(size_t)MROWS * HIDD];
__device__ __half g_qhi[(size_t)MROWS * HIDD];
__device__ __half g_qlo[(size_t)MROWS * HIDD];
__device__ __half g_khi[(size_t)MROWS * HIDD];
__device__ __half g_vthi[(size_t)MROWS * HIDD];   // [b][h*dh][s]
__device__ __half g_chi[(size_t)MROWS * HIDD];
__device__ __half g_clo[(size_t)MROWS * HIDD];
__device__ __half g_wthi[4][(size_t)HIDD * HIDD];   // W^T [N][K] hi (fp16)
__device__ unsigned char g_mask[(size_t)Ss * Ss];
__device__ unsigned char g_bany[NBLK * NBLK];
__device__ int g_flag;

// ======================= PTX helpers (family-portable) =======================
__device__ __forceinline__ uint32_t smem_u32(const void* p) {
    uint32_t a;
    asm("{ .reg .u64 t; cvta.to.shared.u64 t, %1; cvt.u32.u64 %0, t; }"
        : "=r"(a) : "l"(p));
    return a;
}
__device__ __forceinline__ void cp_async16(uint32_t dst, const void* src) {
    asm volatile("cp.async.cg.shared.global [%0], [%1], 16;"
                 :: "r"(dst), "l"(src) : "memory");
}
#define CP_COMMIT() asm volatile("cp.async.commit_group;" ::: "memory")
#define CP_WAIT(n)  asm volatile("cp.async.wait_group %0;" :: "n"(n) : "memory")

__device__ __forceinline__ void ldsm4(uint32_t* r, uint32_t addr) {
    asm volatile("ldmatrix.sync.aligned.m8n8.x4.shared.b16 {%0,%1,%2,%3}, [%4];"
                 : "=r"(r[0]), "=r"(r[1]), "=r"(r[2]), "=r"(r[3]) : "r"(addr));
}
__device__ __forceinline__ void mma16816(float* c, const uint32_t* a, const uint32_t* b) {
    asm volatile(
        "mma.sync.aligned.m16n8k16.row.col.f32.f16.f16.f32 "
        "{%0,%1,%2,%3}, {%4,%5,%6,%7}, {%8,%9}, {%0,%1,%2,%3};"
        : "+f"(c[0]), "+f"(c[1]), "+f"(c[2]), "+f"(c[3])
        : "r"(a[0]), "r"(a[1]), "r"(a[2]), "r"(a[3]), "r"(b[0]), "r"(b[1]));
}

#define SW128(o) ((o) ^ (((o) >> 3) & 0x70))

__device__ __forceinline__ uint32_t pack_h2(float a, float b) {
    __half2 t = __floats2half2_rn(a, b);
    return *(uint32_t*)&t;
}

// ---------------- mask dtype detection + canonicalization ----------------
__global__ void detect_kernel(const unsigned char* __restrict__ raw) {
    int f;
    if (raw[0] == 1 && raw[1] == 1) f = 0;       // u8 / bool
    else if (raw[0] == 1)           f = 1;       // int32
    else                            f = 2;       // float32
    g_flag = f;
}

__global__ void expand_kernel(const void* __restrict__ raw) {
    size_t idx = (size_t)blockIdx.x * blockDim.x + threadIdx.x;
    if (idx >= (size_t)Ss * Ss) return;
    int f = g_flag;
    unsigned char v;
    if (f == 0)      v = ((const unsigned char*)raw)[idx] != 0;
    else if (f == 1) v = ((const int*)raw)[idx] != 0;
    else             v = ((const float*)raw)[idx] != 0.0f;
    g_mask[idx] = v;
}

__global__ void bany_kernel() {
    int qb = blockIdx.y, kb = blockIdx.x;
    int r = threadIdx.x;   // 64 threads
    const unsigned char* row = &g_mask[(size_t)(qb * 64 + r) * Ss + kb * 64];
    int any = 0;
    #pragma unroll 8
    for (int c = 0; c < 64; c++) any |= row[c];
    int res = __syncthreads_or(any);
    if (r == 0) g_bany[qb * NBLK + kb] = res ? 1 : 0;
}

// ---------------- fp32 -> fp16 hi/lo split ----------------
__global__ void split_kernel(const float* __restrict__ in,
                             __half* __restrict__ hi,
                             __half* __restrict__ lo, int n4) {
    int i = blockIdx.x * blockDim.x + threadIdx.x;
    if (i >= n4) return;
    float4 v = ((const float4*)in)[i];
    __half h0 = __float2half_rn(v.x), h1 = __float2half_rn(v.y);
    __half h2 = __float2half_rn(v.z), h3 = __float2half_rn(v.w);
    __half l0 = __float2half_rn(v.x - __half2float(h0));
    __half l1 = __float2half_rn(v.y - __half2float(h1));
    __half l2 = __float2half_rn(v.z - __half2float(h2));
    __half l3 = __float2half_rn(v.w - __half2float(h3));
    ushort4 hv = make_ushort4(__half_as_ushort(h0), __half_as_ushort(h1),
                              __half_as_ushort(h2), __half_as_ushort(h3));
    ushort4 lv = make_ushort4(__half_as_ushort(l0), __half_as_ushort(l1),
                              __half_as_ushort(l2), __half_as_ushort(l3));
    ((ushort4*)hi)[i] = hv;
    ((ushort4*)lo)[i] = lv;
}

// ---------------- transpose: W[K][N] -> T[N][K] fp16 (hi only) ----------------
__global__ void tsplit_kernel(const float* __restrict__ W,
                              __half* __restrict__ Thi) {
    __shared__ float t[32][33];
    int n0 = blockIdx.x * 32, k0 = blockIdx.y * 32;
    int tx = threadIdx.x, ty = threadIdx.y;   // block (32, 8)
    #pragma unroll
    for (int i = 0; i < 4; i++)
        t[ty + i * 8][tx] = W[(size_t)(k0 + ty + i * 8) * HIDD + n0 + tx];
    __syncthreads();
    #pragma unroll
    for (int i = 0; i < 4; i++) {
        float x = t[tx][ty + i * 8];
        Thi[(size_t)(n0 + ty + i * 8) * HIDD + k0 + tx] = __float2half_rn(x);
    }
}

// ---------------- transpose V: g_v[m][n] -> vt[(b*2048+n)][s] fp16 hi ----------
__global__ void vtsplit_kernel(__half* __restrict__ Thi) {
    __shared__ float t[32][33];
    int n0 = blockIdx.x * 32, m0 = blockIdx.y * 32;
    int tx = threadIdx.x, ty = threadIdx.y;   // block (32, 8)
    #pragma unroll
    for (int i = 0; i < 4; i++)
        t[ty + i * 8][tx] = g_v[(size_t)(m0 + ty + i * 8) * HIDD + n0 + tx];
    __syncthreads();
    int b = m0 >> 11;
    int s0 = m0 & 2047;
    #pragma unroll
    for (int i = 0; i < 4; i++) {
        float x = t[tx][ty + i * 8];
        size_t o = ((size_t)b * 2048 + n0 + ty + i * 8) * 2048 + s0 + tx;
        Thi[o] = __float2half_rn(x);
    }
}

// ---------------- HMMA fp16x2 GEMM ----------------
// C = A @ B^T;  A [M][K] split fp16 hi/lo, B [N][K] K-major fp16.
// C += Ahi*B + Alo*B  (fp32 accum).  3-stage cp.async pipeline.
// Epilogue: fp32 C, or fp16 hi/lo pair, or fp16 hi only.
#define GK 2048
#define GN 2048
#define NIT 32
#define GTILE_BYTES 16384
#define GSTAGE (3 * GTILE_BYTES)          // Ahi, Alo, B
#define GSMEM_TOTAL (3 * GSTAGE)          // 147456

__global__ __launch_bounds__(256, 1)
void gemm_hmma_x2(const __half* __restrict__ Ahi,
                  const __half* __restrict__ Alo,
                  const __half* __restrict__ Bh,
                  float* __restrict__ C,
                  __half* __restrict__ Chi,
                  __half* __restrict__ Clo) {
    extern __shared__ char smem[];
    uint32_t sb = smem_u32(smem);
    int tid = threadIdx.x, l = tid & 31, wid = tid >> 5;
    int warp_m = wid & 3, warp_n = wid >> 2;
    int bm = blockIdx.y * 128, bn = blockIdx.x * 128;

    const char* src[3] = {
        (const char*)(Ahi + (size_t)bm * GK),
        (const char*)(Alo + (size_t)bm * GK),
        (const char*)(Bh + (size_t)bn * GK)
    };

    float c[2][8][4];
    #pragma unroll
    for (int i = 0; i < 2; i++)
        #pragma unroll
        for (int j = 0; j < 8; j++)
            #pragma unroll
            for (int k = 0; k < 4; k++) c[i][j][k] = 0.0f;

    int srow[4], scol[4];
    #pragma unroll
    for (int j = 0; j < 4; j++) {
        int v = tid + j * 256;
        srow[j] = v >> 3;
        scol[j] = (v & 7) * 16;
    }

    auto stage_load = [&](int ci, int st) {
        int koff = ci * 128;
        #pragma unroll
        for (int w = 0; w < 3; w++) {
            uint32_t dst = sb + st * GSTAGE + w * GTILE_BYTES;
            const char* s = src[w] + koff;
            #pragma unroll
            for (int j = 0; j < 4; j++) {
                cp_async16(dst + SW128(srow[j] * 128 + scol[j]),
                           s + (size_t)srow[j] * (GK * 2) + scol[j]);
            }
        }
    };

    int rrA = (l & 7) + ((l >> 3) & 1) * 8;
    int kbA = ((l >> 4) & 1) * 16;
    int rrB = (l & 7) + ((l >> 4) & 1) * 8;
    int kbB = ((l >> 3) & 1) * 16;

    stage_load(0, 0);
    CP_COMMIT();
    stage_load(1, 1);
    CP_COMMIT();

    for (int i = 0; i < NIT; i++) {
        __syncthreads();   // protect slot (i+2)%3 (consumed at iter i-1)
        if (i + 2 < NIT) {
            stage_load(i + 2, (i + 2) % 3);
            CP_COMMIT();
            CP_WAIT(2);
        } else if (i + 1 < NIT) {
            CP_WAIT(1);
        } else {
            CP_WAIT(0);
        }
        __syncthreads();

        uint32_t bAh = sb + (i % 3) * GSTAGE;
        uint32_t bAl = bAh + GTILE_BYTES;
        uint32_t bBh = bAh + 2 * GTILE_BYTES;

        #pragma unroll
        for (int ks = 0; ks < 4; ks++) {
            int kk = ks * 32;
            uint32_t afh[2][4], afl[2][4];
            #pragma unroll
            for (int mt = 0; mt < 2; mt++) {
                int rb = (warp_m * 32 + mt * 16 + rrA) * 128;
                uint32_t off = rb + ((kk + kbA) ^ ((rb >> 3) & 0x70));
                ldsm4(afh[mt], bAh + off);
                ldsm4(afl[mt], bAl + off);
            }
            uint32_t bf[8][2];
            #pragma unroll
            for (int np = 0; np < 4; np++) {
                int rb = (warp_n * 64 + np * 16 + rrB) * 128;
                uint32_t off = rb + ((kk + kbB) ^ ((rb >> 3) & 0x70));
                uint32_t t[4];
                ldsm4(t, bBh + off);
                bf[np * 2][0] = t[0]; bf[np * 2][1] = t[1];
                bf[np * 2 + 1][0] = t[2]; bf[np * 2 + 1][1] = t[3];
            }
            #pragma unroll
            for (int mt = 0; mt < 2; mt++)
                #pragma unroll
                for (int nt = 0; nt < 8; nt++) {
                    mma16816(c[mt][nt], afh[mt], bf[nt]);
                    mma16816(c[mt][nt], afl[mt], bf[nt]);
                }
        }
    }

    // epilogue
    #pragma unroll
    for (int mt = 0; mt < 2; mt++) {
        #pragma unroll
        for (int nt = 0; nt < 8; nt++) {
            int m0 = bm + warp_m * 32 + mt * 16 + (l >> 2);
            int cn = bn + warp_n * 64 + nt * 8 + (l & 3) * 2;
            size_t i0 = (size_t)m0 * GN + cn, i1 = (size_t)(m0 + 8) * GN + cn;
            float v0 = c[mt][nt][0], v1 = c[mt][nt][1];
            float v2 = c[mt][nt][2], v3 = c[mt][nt][3];
            if (Chi) {
                __half h0 = __float2half_rn(v0), h1 = __float2half_rn(v1);
                __half h2 = __float2half_rn(v2), h3 = __float2half_rn(v3);
                *(uint32_t*)&Chi[i0] = pack_h2(__half2float(h0), __half2float(h1));
                *(uint32_t*)&Chi[i1] = pack_h2(__half2float(h2), __half2float(h3));
                if (Clo) {
                    *(uint32_t*)&Clo[i0] = pack_h2(v0 - __half2float(h0), v1 - __half2float(h1));
                    *(uint32_t*)&Clo[i1] = pack_h2(v2 - __half2float(h2), v3 - __half2float(h3));
                }
            } else {
                *(float2*)&C[i0] = make_float2(v0, v1);
                *(float2*)&C[i1] = make_float2(v2, v3);
            }
        }
    }
}

// ---------------- HMMA fp16x2 flash attention ----------------
// grid (qb=32, h=16, b=2), 128 threads (4 warps). Warp w owns q rows [w*16, w*16+16).
// S = Qhi·K + Qlo·K ; O += Phi·V + Plo·V (K, V fp16 hi only)
#define A_SQ       0                       // Q: hi c0, hi c1, lo c0, lo c1 (4 x 8KB)
#define A_KV(st)   (32768 + (st) * 32768)  // Khi c0 (8KB), Khi c1 (8KB), Vhi (16KB)
#define A_P        98304                   // Phi 8KB, Plo 8KB
#define A_MASK(st) (114688 + (st) * 4096)
#define A_LIST     122880                  // int count + int[32]
#define ATTN2_SMEM 123136

__global__ __launch_bounds__(128, 1)
void attn_mma() {
    extern __shared__ char sm[];
    uint32_t sb = smem_u32(sm);
    int tid = threadIdx.x, l = tid & 31, w = tid >> 5;
    int qb = blockIdx.x, h = blockIdx.y, b = blockIdx.z;

    int rrA = (l & 7) + ((l >> 3) & 1) * 8;
    int kbA = ((l >> 4) & 1) * 16;
    int rrB = (l & 7) + ((l >> 4) & 1) * 8;
    int kbB = ((l >> 3) & 1) * 16;

    const size_t qrow_base = ((size_t)b * Ss + qb * 64) * HIDD;   // elements
    const size_t colb_base = (size_t)h * 256;                     // bytes within row

    // ---- load Q tiles (hi c0, hi c1, lo c0, lo c1) ----
    {
        #pragma unroll
        for (int t = 0; t < 4; t++) {
            const char* base = (const char*)((t < 2) ? g_qhi : g_qlo) + qrow_base * 2
                               + colb_base + (t & 1) * 128;
            uint32_t dst = sb + A_SQ + t * 8192;
            #pragma unroll
            for (int j = 0; j < 4; j++) {
                int vec = tid + j * 128;
                int row = vec >> 3, cbt = (vec & 7) * 16;
                cp_async16(dst + SW128(row * 128 + cbt),
                           base + (size_t)row * 4096 + cbt);
            }
        }
        CP_COMMIT();
    }

    // ---- build visible-kb list ----
    int* sList = (int*)(sm + A_LIST);
    if (tid == 0) {
        int c = 0;
        for (int kb = 0; kb < NBLK; kb++)
            if (g_bany[qb * NBLK + kb]) sList[1 + c++] = kb;
        sList[0] = c;
    }
    __syncthreads();
    int cnt = sList[0];

    // ---- KV + mask prefetch ----
    auto prefetch = [&](int kb, int st) {
        uint32_t kvb = sb + A_KV(st);
        size_t krow = ((size_t)b * Ss + kb * 64) * HIDD * 2;   // bytes
        #pragma unroll
        for (int t = 0; t < 2; t++) {     // Khi chunk 0, chunk 1
            const char* base = (const char*)g_khi + krow + colb_base + t * 128;
            uint32_t dst = kvb + t * 8192;
            #pragma unroll
            for (int j = 0; j < 4; j++) {
                int vec = tid + j * 128;
                int row = vec >> 3, cbt = (vec & 7) * 16;
                cp_async16(dst + SW128(row * 128 + cbt),
                           base + (size_t)row * 4096 + cbt);
            }
        }
        size_t vrow = ((size_t)b * 2048 + h * 128) * 2048 * 2;  // bytes; +dh*4096
        {
            const char* base = (const char*)g_vthi + vrow + kb * 128;
            uint32_t dst = kvb + 16384;
            #pragma unroll
            for (int j = 0; j < 8; j++) {
                int vec = tid + j * 128;
                int row = vec >> 3, cbt = (vec & 7) * 16;
                cp_async16(dst + SW128(row * 128 + cbt),
                           base + (size_t)row * 4096 + cbt);
            }
        }
        {
            const char* base = (const char*)g_mask + (size_t)(qb * 64) * Ss + kb * 64;
            uint32_t dst = sb + A_MASK(st);
            #pragma unroll
            for (int j = 0; j < 2; j++) {
                int vec = tid + j * 128;
                int row = vec >> 2, cbt = (vec & 3) * 16;
                cp_async16(dst + row * 64 + cbt, base + (size_t)row * Ss + cbt);
            }
        }
    };

    prefetch(sList[1], 0);
    CP_COMMIT();

    // ---- state ----
    float o[16][4];
    #pragma unroll
    for (int i = 0; i < 16; i++)
        #pragma unroll
        for (int j = 0; j < 4; j++) o[i][j] = 0.0f;
    float m0r = -1e30f, m1r = -1e30f, l0r = 0.0f, l1r = 0.0f;

    int qrow0 = w * 16;
    int r0l = qrow0 + (l >> 2);

    for (int i = 0; i < cnt; i++) {
        int st = i & 1;
        __syncthreads();   // all warps done with stage st^1 (iter i-1) before refill
        if (i + 1 < cnt) {
            prefetch(sList[1 + i + 1], st ^ 1);
            CP_COMMIT();
            CP_WAIT(1);
        } else {
            CP_WAIT(0);
        }
        __syncthreads();

        uint32_t kvb = sb + A_KV(st);

        // ---- S = Q @ K^T (fp16x2) ----
        float s[8][4];
        #pragma unroll
        for (int nt = 0; nt < 8; nt++)
            #pragma unroll
            for (int j = 0; j < 4; j++) s[nt][j] = 0.0f;

        #pragma unroll
        for (int chunk = 0; chunk < 2; chunk++) {
            uint32_t bQh = sb + A_SQ + chunk * 8192;
            uint32_t bQl = sb + A_SQ + 16384 + chunk * 8192;
            uint32_t bKh = kvb + chunk * 8192;
            #pragma unroll
            for (int ks = 0; ks < 4; ks++) {
                int kk = ks * 32;
                int rowA = qrow0 + rrA;
                uint32_t offA = rowA * 128 + ((kk + kbA) ^ ((rowA & 7) << 4));
                uint32_t ah[4], al[4];
                ldsm4(ah, bQh + offA);
                ldsm4(al, bQl + offA);
                #pragma unroll
                for (int np = 0; np < 4; np++) {
                    int rowB = np * 16 + rrB;
                    uint32_t offB = rowB * 128 + ((kk + kbB) ^ ((rowB & 7) << 4));
                    uint32_t th[4];
                    ldsm4(th, bKh + offB);
                    uint32_t bh0[2] = {th[0], th[1]}, bh1[2] = {th[2], th[3]};
                    mma16816(s[np * 2], ah, bh0);
                    mma16816(s[np * 2], al, bh0);
                    mma16816(s[np * 2 + 1], ah, bh1);
                    mma16816(s[np * 2 + 1], al, bh1);
                }
            }
        }

        // ---- mask + scale + online softmax ----
        const unsigned char* mk = (const unsigned char*)(sm + A_MASK(st))
                                  + r0l * 64 + (l & 3) * 2;
        float mx0 = -1e30f, mx1 = -1e30f;
        #pragma unroll
        for (int nt = 0; nt < 8; nt++) {
            int cb = nt * 8;
            float t00 = mk[cb]       ? s[nt][0] * SCALE_F : -1e30f;
            float t01 = mk[cb + 1]   ? s[nt][1] * SCALE_F : -1e30f;
            float t10 = mk[cb + 512] ? s[nt][2] * SCALE_F : -1e30f;
            float t11 = mk[cb + 513] ? s[nt][3] * SCALE_F : -1e30f;
            s[nt][0] = t00; s[nt][1] = t01; s[nt][2] = t10; s[nt][3] = t11;
            mx0 = fmaxf(mx0, fmaxf(t00, t01));
            mx1 = fmaxf(mx1, fmaxf(t10, t11));
        }
        mx0 = fmaxf(mx0, __shfl_xor_sync(0xffffffffu, mx0, 1));
        mx0 = fmaxf(mx0, __shfl_xor_sync(0xffffffffu, mx0, 2));
        mx1 = fmaxf(mx1, __shfl_xor_sync(0xffffffffu, mx1, 1));
        mx1 = fmaxf(mx1, __shfl_xor_sync(0xffffffffu, mx1, 2));
        float mn0 = fmaxf(m0r, mx0), mn1 = fmaxf(m1r, mx1);
        float sc0 = __expf(m0r - mn0), sc1 = __expf(m1r - mn1);
        m0r = mn0; m1r = mn1;

        // ---- P = exp(S - m), write hi/lo fp16 to smem (full-column swizzle) ----
        float sum0 = 0.0f, sum1 = 0.0f;
        int colb = (l & 3) * 4;
        int sw0 = (r0l & 7) << 4;                 // same for r0l and r0l+8
        uint32_t rb0 = r0l * 128;
        uint32_t rb1 = (r0l + 8) * 128;
        #pragma unroll
        for (int nt = 0; nt < 8; nt++) {
            float p00 = __expf(s[nt][0] - mn0);
            float p01 = __expf(s[nt][1] - mn0);
            float p10 = __expf(s[nt][2] - mn1);
            float p11 = __expf(s[nt][3] - mn1);
            sum0 += p00 + p01;
            sum1 += p10 + p11;
            __half h00 = __float2half_rn(p00), h01 = __float2half_rn(p01);
            __half h10 = __float2half_rn(p10), h11 = __float2half_rn(p11);
            uint32_t colsw = (uint32_t)((nt * 16 + colb) ^ sw0);
            uint32_t a0 = rb0 + colsw;
            uint32_t a1 = rb1 + colsw;
            *(uint32_t*)(sm + A_P + a0) = pack_h2(__half2float(h00), __half2float(h01));
            *(uint32_t*)(sm + A_P + a1) = pack_h2(__half2float(h10), __half2float(h11));
            *(uint32_t*)(sm + A_P + 8192 + a0) =
                pack_h2(p00 - __half2float(h00), p01 - __half2float(h01));
            *(uint32_t*)(sm + A_P + 8192 + a1) =
                pack_h2(p10 - __half2float(h10), p11 - __half2float(h11));
        }
        sum0 += __shfl_xor_sync(0xffffffffu, sum0, 1);
        sum0 += __shfl_xor_sync(0xffffffffu, sum0, 2);
        sum1 += __shfl_xor_sync(0xffffffffu, sum1, 1);
        sum1 += __shfl_xor_sync(0xffffffffu, sum1, 2);
        l0r = l0r * sc0 + sum0;
        l1r = l1r * sc1 + sum1;

        // ---- O rescale + O += P @ Vt (fp16x2) ----
        #pragma unroll
        for (int nt = 0; nt < 16; nt++) {
            o[nt][0] *= sc0; o[nt][1] *= sc0;
            o[nt][2] *= sc1; o[nt][3] *= sc1;
        }
        __syncwarp();

        uint32_t bPh = sb + A_P, bPl = sb + A_P + 8192;
        uint32_t bVh = kvb + 16384;
        #pragma unroll
        for (int ks = 0; ks < 4; ks++) {
            int kk = ks * 32;
            int rowA = qrow0 + rrA;
            uint32_t offA = rowA * 128 + ((kk + kbA) ^ ((rowA & 7) << 4));
            uint32_t ph[4], pl[4];
            ldsm4(ph, bPh + offA);
            ldsm4(pl, bPl + offA);
            #pragma unroll
            for (int np = 0; np < 8; np++) {
                int rowB = np * 16 + rrB;
                uint32_t offB = rowB * 128 + ((kk + kbB) ^ ((rowB & 7) << 4));
                uint32_t th[4];
                ldsm4(th, bVh + offB);
                uint32_t vh0[2] = {th[0], th[1]}, vh1[2] = {th[2], th[3]};
                mma16816(o[np * 2], ph, vh0);
                mma16816(o[np * 2], pl, vh0);
                mma16816(o[np * 2 + 1], ph, vh1);
                mma16816(o[np * 2 + 1], pl, vh1);
            }
        }
    }

    // ---- epilogue: O /= l, write ctx hi/lo fp16 ----
    float inv0 = 1.0f / l0r, inv1 = 1.0f / l1r;
    size_t row0 = (size_t)b * Ss + qb * 64 + qrow0 + (l >> 2);
    size_t row1 = row0 + 8;
    int cn0 = h * 128 + (l & 3) * 2;
    #pragma unroll
    for (int nt = 0; nt < 16; nt++) {
        int cn = cn0 + nt * 8;
        float v0 = o[nt][0] * inv0, v1 = o[nt][1] * inv0;
        float v2 = o[nt][2] * inv1, v3 = o[nt][3] * inv1;
        __half h0 = __float2half_rn(v0), h1 = __float2half_rn(v1);
        __half h2 = __float2half_rn(v2), h3 = __float2half_rn(v3);
        size_t i0 = row0 * HIDD + cn, i1 = row1 * HIDD + cn;
        *(uint32_t*)&g_chi[i0] = pack_h2(__half2float(h0), __half2float(h1));
        *(uint32_t*)&g_chi[i1] = pack_h2(__half2float(h2), __half2float(h3));
        *(uint32_t*)&g_clo[i0] = pack_h2(v0 - __half2float(h0), v1 - __half2float(h1));
        *(uint32_t*)&g_clo[i1] = pack_h2(v2 - __half2float(h2), v3 - __half2float(h3));
    }
}

// ---------------- launch ----------------
extern "C" void kernel_launch(void* const* d_in, const int* in_sizes, int n_in,
                              void* d_out, int out_size) {
    const float* X  = (const float*)d_in[0];
    const float* Wq = (const float*)d_in[1];
    const float* Wk = (const float*)d_in[2];
    const float* Wv = (const float*)d_in[3];
    const float* Wo = (const float*)d_in[4];
    const void*  Mraw = d_in[5];
    float* out = (float*)d_out;

    cudaFuncSetAttribute(gemm_hmma_x2,
                         cudaFuncAttributeMaxDynamicSharedMemorySize, GSMEM_TOTAL);
    cudaFuncSetAttribute(attn_mma,
                         cudaFuncAttributeMaxDynamicSharedMemorySize, ATTN2_SMEM);

    // mask canonicalization
    detect_kernel<<<1, 1>>>((const unsigned char*)Mraw);
    expand_kernel<<<(Ss * Ss) / 256, 256>>>(Mraw);
    bany_kernel<<<dim3(NBLK, NBLK), 64>>>();

    // scratch pointers
    float* pv;
    __half *pxhi, *pxlo, *pqhi, *pqlo, *pkhi, *pvthi, *pchi, *pclo, *pwhi;
    cudaGetSymbolAddress((void**)&pv,    g_v);
    cudaGetSymbolAddress((void**)&pxhi,  g_xhi);
    cudaGetSymbolAddress((void**)&pxlo,  g_xlo);
    cudaGetSymbolAddress((void**)&pqhi,  g_qhi);
    cudaGetSymbolAddress((void**)&pqlo,  g_qlo);
    cudaGetSymbolAddress((void**)&pkhi,  g_khi);
    cudaGetSymbolAddress((void**)&pvthi, g_vthi);
    cudaGetSymbolAddress((void**)&pchi,  g_chi);
    cudaGetSymbolAddress((void**)&pclo,  g_clo);
    cudaGetSymbolAddress((void**)&pwhi,  g_wthi);

    const size_t WSZ = (size_t)HIDD * HIDD;

    // operand preparation
    split_kernel<<<(MROWS * HIDD / 4 + 255) / 256, 256>>>(X, pxhi, pxlo, MROWS * HIDD / 4);
    dim3 tgrid(HIDD / 32, HIDD / 32);
    tsplit_kernel<<<tgrid, dim3(32, 8)>>>(Wq, pwhi + 0 * WSZ);
    tsplit_kernel<<<tgrid, dim3(32, 8)>>>(Wk, pwhi + 1 * WSZ);
    tsplit_kernel<<<tgrid, dim3(32, 8)>>>(Wv, pwhi + 2 * WSZ);
    tsplit_kernel<<<tgrid, dim3(32, 8)>>>(Wo, pwhi + 3 * WSZ);

    // projections (fp16x2)
    dim3 ggrid(GN / 128, MROWS / 128);
    gemm_hmma_x2<<<ggrid, 256, GSMEM_TOTAL>>>(pxhi, pxlo, pwhi + 0 * WSZ,
                                              nullptr, pqhi, pqlo);
    gemm_hmma_x2<<<ggrid, 256, GSMEM_TOTAL>>>(pxhi, pxlo, pwhi + 1 * WSZ,
                                              nullptr, pkhi, nullptr);
    gemm_hmma_x2<<<ggrid, 256, GSMEM_TOTAL>>>(pxhi, pxlo, pwhi + 2 * WSZ,
                                              pv, nullptr, nullptr);
    vtsplit_kernel<<<dim3(HIDD / 32, MROWS / 32), dim3(32, 8)>>>(pvthi);

    // attention (fp16x2)
    attn_mma<<<dim3(NBLK, Hh, Bb), 128, ATTN2_SMEM>>>();

    // output projection
    gemm_hmma_x2<<<ggrid, 256, GSMEM_TOTAL>>>(pchi, pclo, pwhi + 3 * WSZ,
                                              out, nullptr, nullptr);
}

// round 7
// speedup vs baseline: 4.6906x; 1.0630x over previous
#include <cuda_runtime.h>
#include <cuda_fp16.h>
#include <stdint.h>
#include <math.h>

// Problem constants
#define Bb    2
#define Ss    2048
#define HIDD  2048
#define Hh    16
#define DHh   128
#define NBLK  32        // 2048 / 64
#define MROWS 4096      // B*S
#define SCALE_F 0.08838834764831845f   // 1/sqrt(128)

// ---------------- scratch (static device allocations) ----------------
__device__ __half g_xhi[(size_t)MROWS * HIDD];
__device__ __half g_xlo[(size_t)MROWS * HIDD];
__device__ __half g_qhi[(size_t)MROWS * HIDD];
__device__ __half g_qlo[(size_t)MROWS * HIDD];
__device__ __half g_khi[(size_t)MROWS * HIDD];
__device__ __half g_vh [(size_t)MROWS * HIDD];    // V projection, [m][n] fp16
__device__ __half g_vthi[(size_t)MROWS * HIDD];   // [b][h*dh][s]
__device__ __half g_chi[(size_t)MROWS * HIDD];
__device__ __half g_clo[(size_t)MROWS * HIDD];
__device__ __half g_wthi[4][(size_t)HIDD * HIDD];   // W^T [N][K] fp16
__device__ unsigned char g_mask[(size_t)Ss * Ss];
__device__ unsigned char g_bany[NBLK * NBLK];
__device__ int g_flag;

// ======================= PTX helpers (family-portable) =======================
__device__ __forceinline__ uint32_t smem_u32(const void* p) {
    uint32_t a;
    asm("{ .reg .u64 t; cvta.to.shared.u64 t, %1; cvt.u32.u64 %0, t; }"
        : "=r"(a) : "l"(p));
    return a;
}
__device__ __forceinline__ void cp_async16(uint32_t dst, const void* src) {
    asm volatile("cp.async.cg.shared.global [%0], [%1], 16;"
                 :: "r"(dst), "l"(src) : "memory");
}
#define CP_COMMIT() asm volatile("cp.async.commit_group;" ::: "memory")
#define CP_WAIT(n)  asm volatile("cp.async.wait_group %0;" :: "n"(n) : "memory")

__device__ __forceinline__ void ldsm4(uint32_t* r, uint32_t addr) {
    asm volatile("ldmatrix.sync.aligned.m8n8.x4.shared.b16 {%0,%1,%2,%3}, [%4];"
                 : "=r"(r[0]), "=r"(r[1]), "=r"(r[2]), "=r"(r[3]) : "r"(addr));
}
__device__ __forceinline__ void mma16816(float* c, const uint32_t* a, const uint32_t* b) {
    asm volatile(
        "mma.sync.aligned.m16n8k16.row.col.f32.f16.f16.f32 "
        "{%0,%1,%2,%3}, {%4,%5,%6,%7}, {%8,%9}, {%0,%1,%2,%3};"
        : "+f"(c[0]), "+f"(c[1]), "+f"(c[2]), "+f"(c[3])
        : "r"(a[0]), "r"(a[1]), "r"(a[2]), "r"(a[3]), "r"(b[0]), "r"(b[1]));
}

#define SW128(o) ((o) ^ (((o) >> 3) & 0x70))

__device__ __forceinline__ uint32_t pack_h2(float a, float b) {
    __half2 t = __floats2half2_rn(a, b);
    return *(uint32_t*)&t;
}

// ---------------- mask dtype detection + canonicalization ----------------
__global__ void detect_kernel(const unsigned char* __restrict__ raw) {
    int f;
    if (raw[0] == 1 && raw[1] == 1) f = 0;       // u8 / bool
    else if (raw[0] == 1)           f = 1;       // int32
    else                            f = 2;       // float32
    g_flag = f;
}

__global__ void expand_kernel(const void* __restrict__ raw) {
    size_t idx = (size_t)blockIdx.x * blockDim.x + threadIdx.x;
    if (idx >= (size_t)Ss * Ss) return;
    int f = g_flag;
    unsigned char v;
    if (f == 0)      v = ((const unsigned char*)raw)[idx] != 0;
    else if (f == 1) v = ((const int*)raw)[idx] != 0;
    else             v = ((const float*)raw)[idx] != 0.0f;
    g_mask[idx] = v;
}

__global__ void bany_kernel() {
    int qb = blockIdx.y, kb = blockIdx.x;
    int r = threadIdx.x;   // 64 threads
    const unsigned char* row = &g_mask[(size_t)(qb * 64 + r) * Ss + kb * 64];
    int any = 0;
    #pragma unroll 8
    for (int c = 0; c < 64; c++) any |= row[c];
    int res = __syncthreads_or(any);
    if (r == 0) g_bany[qb * NBLK + kb] = res ? 1 : 0;
}

// ---------------- fp32 -> fp16 hi/lo split ----------------
__global__ void split_kernel(const float* __restrict__ in,
                             __half* __restrict__ hi,
                             __half* __restrict__ lo, int n4) {
    int i = blockIdx.x * blockDim.x + threadIdx.x;
    if (i >= n4) return;
    float4 v = ((const float4*)in)[i];
    __half h0 = __float2half_rn(v.x), h1 = __float2half_rn(v.y);
    __half h2 = __float2half_rn(v.z), h3 = __float2half_rn(v.w);
    __half l0 = __float2half_rn(v.x - __half2float(h0));
    __half l1 = __float2half_rn(v.y - __half2float(h1));
    __half l2 = __float2half_rn(v.z - __half2float(h2));
    __half l3 = __float2half_rn(v.w - __half2float(h3));
    ushort4 hv = make_ushort4(__half_as_ushort(h0), __half_as_ushort(h1),
                              __half_as_ushort(h2), __half_as_ushort(h3));
    ushort4 lv = make_ushort4(__half_as_ushort(l0), __half_as_ushort(l1),
                              __half_as_ushort(l2), __half_as_ushort(l3));
    ((ushort4*)hi)[i] = hv;
    ((ushort4*)lo)[i] = lv;
}

// ---------------- batched transpose: W[K][N] -> T[N][K] fp16, z = which W ----
__global__ void tsplit4_kernel(const float* __restrict__ W0,
                               const float* __restrict__ W1,
                               const float* __restrict__ W2,
                               const float* __restrict__ W3) {
    __shared__ float t[32][33];
    int z = blockIdx.z;
    const float* W = (z == 0) ? W0 : (z == 1) ? W1 : (z == 2) ? W2 : W3;
    __half* Thi = g_wthi[z];
    int n0 = blockIdx.x * 32, k0 = blockIdx.y * 32;
    int tx = threadIdx.x, ty = threadIdx.y;   // block (32, 8)
    #pragma unroll
    for (int i = 0; i < 4; i++)
        t[ty + i * 8][tx] = W[(size_t)(k0 + ty + i * 8) * HIDD + n0 + tx];
    __syncthreads();
    #pragma unroll
    for (int i = 0; i < 4; i++)
        Thi[(size_t)(n0 + ty + i * 8) * HIDD + k0 + tx] =
            __float2half_rn(t[tx][ty + i * 8]);
}

// ---------------- transpose V (fp16): g_vh[m][n] -> vt[(b*2048+n)][s] ---------
__global__ void vtsplit_kernel() {
    __shared__ __half t[32][34];
    int n0 = blockIdx.x * 32, m0 = blockIdx.y * 32;
    int tx = threadIdx.x, ty = threadIdx.y;   // block (32, 8)
    #pragma unroll
    for (int i = 0; i < 4; i++)
        t[ty + i * 8][tx] = g_vh[(size_t)(m0 + ty + i * 8) * HIDD + n0 + tx];
    __syncthreads();
    int b = m0 >> 11;
    int s0 = m0 & 2047;
    #pragma unroll
    for (int i = 0; i < 4; i++) {
        size_t o = ((size_t)b * 2048 + n0 + ty + i * 8) * 2048 + s0 + tx;
        g_vthi[o] = t[tx][ty + i * 8];
    }
}

// ---------------- HMMA fp16x2 GEMM core ----------------
// C = A @ B^T;  A [M][K] split fp16 hi/lo, B [N][K] K-major fp16.
// C += Ahi*B + Alo*B  (fp32 accum).  3-stage cp.async pipeline.
#define GK 2048
#define GN 2048
#define NIT 32
#define GTILE_BYTES 16384
#define GSTAGE (3 * GTILE_BYTES)          // Ahi, Alo, B
#define GSMEM_TOTAL (3 * GSTAGE)          // 147456

__device__ __forceinline__
void gemm_body(const __half* __restrict__ Ahi,
               const __half* __restrict__ Alo,
               const __half* __restrict__ Bh,
               float* __restrict__ C,
               __half* __restrict__ Chi,
               __half* __restrict__ Clo,
               char* smem) {
    uint32_t sb = smem_u32(smem);
    int tid = threadIdx.x, l = tid & 31, wid = tid >> 5;
    int warp_m = wid & 3, warp_n = wid >> 2;
    int bm = blockIdx.y * 128, bn = blockIdx.x * 128;

    const char* src[3] = {
        (const char*)(Ahi + (size_t)bm * GK),
        (const char*)(Alo + (size_t)bm * GK),
        (const char*)(Bh + (size_t)bn * GK)
    };

    float c[2][8][4];
    #pragma unroll
    for (int i = 0; i < 2; i++)
        #pragma unroll
        for (int j = 0; j < 8; j++)
            #pragma unroll
            for (int k = 0; k < 4; k++) c[i][j][k] = 0.0f;

    int srow[4], scol[4];
    #pragma unroll
    for (int j = 0; j < 4; j++) {
        int v = tid + j * 256;
        srow[j] = v >> 3;
        scol[j] = (v & 7) * 16;
    }

    auto stage_load = [&](int ci, int st) {
        int koff = ci * 128;
        #pragma unroll
        for (int w = 0; w < 3; w++) {
            uint32_t dst = sb + st * GSTAGE + w * GTILE_BYTES;
            const char* s = src[w] + koff;
            #pragma unroll
            for (int j = 0; j < 4; j++) {
                cp_async16(dst + SW128(srow[j] * 128 + scol[j]),
                           s + (size_t)srow[j] * (GK * 2) + scol[j]);
            }
        }
    };

    int rrA = (l & 7) + ((l >> 3) & 1) * 8;
    int kbA = ((l >> 4) & 1) * 16;
    int rrB = (l & 7) + ((l >> 4) & 1) * 8;
    int kbB = ((l >> 3) & 1) * 16;

    stage_load(0, 0);
    CP_COMMIT();
    stage_load(1, 1);
    CP_COMMIT();

    for (int i = 0; i < NIT; i++) {
        __syncthreads();   // protect slot (i+2)%3 (consumed at iter i-1)
        if (i + 2 < NIT) {
            stage_load(i + 2, (i + 2) % 3);
            CP_COMMIT();
            CP_WAIT(2);
        } else if (i + 1 < NIT) {
            CP_WAIT(1);
        } else {
            CP_WAIT(0);
        }
        __syncthreads();

        uint32_t bAh = sb + (i % 3) * GSTAGE;
        uint32_t bAl = bAh + GTILE_BYTES;
        uint32_t bBh = bAh + 2 * GTILE_BYTES;

        #pragma unroll
        for (int ks = 0; ks < 4; ks++) {
            int kk = ks * 32;
            uint32_t afh[2][4], afl[2][4];
            #pragma unroll
            for (int mt = 0; mt < 2; mt++) {
                int rb = (warp_m * 32 + mt * 16 + rrA) * 128;
                uint32_t off = rb + ((kk + kbA) ^ ((rb >> 3) & 0x70));
                ldsm4(afh[mt], bAh + off);
                ldsm4(afl[mt], bAl + off);
            }
            uint32_t bf[8][2];
            #pragma unroll
            for (int np = 0; np < 4; np++) {
                int rb = (warp_n * 64 + np * 16 + rrB) * 128;
                uint32_t off = rb + ((kk + kbB) ^ ((rb >> 3) & 0x70));
                uint32_t t[4];
                ldsm4(t, bBh + off);
                bf[np * 2][0] = t[0]; bf[np * 2][1] = t[1];
                bf[np * 2 + 1][0] = t[2]; bf[np * 2 + 1][1] = t[3];
            }
            #pragma unroll
            for (int mt = 0; mt < 2; mt++)
                #pragma unroll
                for (int nt = 0; nt < 8; nt++) {
                    mma16816(c[mt][nt], afh[mt], bf[nt]);
                    mma16816(c[mt][nt], afl[mt], bf[nt]);
                }
        }
    }

    // epilogue
    #pragma unroll
    for (int mt = 0; mt < 2; mt++) {
        #pragma unroll
        for (int nt = 0; nt < 8; nt++) {
            int m0 = bm + warp_m * 32 + mt * 16 + (l >> 2);
            int cn = bn + warp_n * 64 + nt * 8 + (l & 3) * 2;
            size_t i0 = (size_t)m0 * GN + cn, i1 = (size_t)(m0 + 8) * GN + cn;
            float v0 = c[mt][nt][0], v1 = c[mt][nt][1];
            float v2 = c[mt][nt][2], v3 = c[mt][nt][3];
            if (Chi) {
                __half h0 = __float2half_rn(v0), h1 = __float2half_rn(v1);
                __half h2 = __float2half_rn(v2), h3 = __float2half_rn(v3);
                *(uint32_t*)&Chi[i0] = pack_h2(__half2float(h0), __half2float(h1));
                *(uint32_t*)&Chi[i1] = pack_h2(__half2float(h2), __half2float(h3));
                if (Clo) {
                    *(uint32_t*)&Clo[i0] = pack_h2(v0 - __half2float(h0), v1 - __half2float(h1));
                    *(uint32_t*)&Clo[i1] = pack_h2(v2 - __half2float(h2), v3 - __half2float(h3));
                }
            } else {
                *(float2*)&C[i0] = make_float2(v0, v1);
                *(float2*)&C[i1] = make_float2(v2, v3);
            }
        }
    }
}

// batched QKV projection: z=0 -> Q (hi/lo), z=1 -> K (hi), z=2 -> V (hi)
__global__ __launch_bounds__(256, 1)
void gemm_qkv() {
    extern __shared__ char smem[];
    int z = blockIdx.z;
    const __half* B = g_wthi[z];
    __half* Chi = (z == 0) ? g_qhi : (z == 1) ? g_khi : g_vh;
    __half* Clo = (z == 0) ? g_qlo : nullptr;
    gemm_body(g_xhi, g_xlo, B, nullptr, Chi, Clo, smem);
}

// output projection: fp32 out
__global__ __launch_bounds__(256, 1)
void gemm_out(float* __restrict__ C) {
    extern __shared__ char smem[];
    gemm_body(g_chi, g_clo, g_wthi[3], C, nullptr, nullptr, smem);
}

// ---------------- HMMA fp16x2 flash attention ----------------
// grid (qb=32, h=16, b=2), 128 threads (4 warps). Warp w owns q rows [w*16, w*16+16).
// S = Qhi·K + Qlo·K ; O += Phi·V + Plo·V (K, V fp16 hi only)
#define A_SQ       0                       // Q: hi c0, hi c1, lo c0, lo c1 (4 x 8KB)
#define A_KV(st)   (32768 + (st) * 32768)  // Khi c0 (8KB), Khi c1 (8KB), Vhi (16KB)
#define A_P        98304                   // Phi 8KB, Plo 8KB
#define A_MASK(st) (114688 + (st) * 4096)
#define A_LIST     122880                  // int count + int[32]
#define ATTN2_SMEM 123136

__global__ __launch_bounds__(128, 1)
void attn_mma() {
    extern __shared__ char sm[];
    uint32_t sb = smem_u32(sm);
    int tid = threadIdx.x, l = tid & 31, w = tid >> 5;
    int qb = blockIdx.x, h = blockIdx.y, b = blockIdx.z;

    int rrA = (l & 7) + ((l >> 3) & 1) * 8;
    int kbA = ((l >> 4) & 1) * 16;
    int rrB = (l & 7) + ((l >> 4) & 1) * 8;
    int kbB = ((l >> 3) & 1) * 16;

    const size_t qrow_base = ((size_t)b * Ss + qb * 64) * HIDD;   // elements
    const size_t colb_base = (size_t)h * 256;                     // bytes within row

    // ---- load Q tiles (hi c0, hi c1, lo c0, lo c1) ----
    {
        #pragma unroll
        for (int t = 0; t < 4; t++) {
            const char* base = (const char*)((t < 2) ? g_qhi : g_qlo) + qrow_base * 2
                               + colb_base + (t & 1) * 128;
            uint32_t dst = sb + A_SQ + t * 8192;
            #pragma unroll
            for (int j = 0; j < 4; j++) {
                int vec = tid + j * 128;
                int row = vec >> 3, cbt = (vec & 7) * 16;
                cp_async16(dst + SW128(row * 128 + cbt),
                           base + (size_t)row * 4096 + cbt);
            }
        }
        CP_COMMIT();
    }

    // ---- build visible-kb list ----
    int* sList = (int*)(sm + A_LIST);
    if (tid == 0) {
        int c = 0;
        for (int kb = 0; kb < NBLK; kb++)
            if (g_bany[qb * NBLK + kb]) sList[1 + c++] = kb;
        sList[0] = c;
    }
    __syncthreads();
    int cnt = sList[0];

    // ---- KV + mask prefetch ----
    auto prefetch = [&](int kb, int st) {
        uint32_t kvb = sb + A_KV(st);
        size_t krow = ((size_t)b * Ss + kb * 64) * HIDD * 2;   // bytes
        #pragma unroll
        for (int t = 0; t < 2; t++) {     // Khi chunk 0, chunk 1
            const char* base = (const char*)g_khi + krow + colb_base + t * 128;
            uint32_t dst = kvb + t * 8192;
            #pragma unroll
            for (int j = 0; j < 4; j++) {
                int vec = tid + j * 128;
                int row = vec >> 3, cbt = (vec & 7) * 16;
                cp_async16(dst + SW128(row * 128 + cbt),
                           base + (size_t)row * 4096 + cbt);
            }
        }
        size_t vrow = ((size_t)b * 2048 + h * 128) * 2048 * 2;  // bytes; +dh*4096
        {
            const char* base = (const char*)g_vthi + vrow + kb * 128;
            uint32_t dst = kvb + 16384;
            #pragma unroll
            for (int j = 0; j < 8; j++) {
                int vec = tid + j * 128;
                int row = vec >> 3, cbt = (vec & 7) * 16;
                cp_async16(dst + SW128(row * 128 + cbt),
                           base + (size_t)row * 4096 + cbt);
            }
        }
        {
            const char* base = (const char*)g_mask + (size_t)(qb * 64) * Ss + kb * 64;
            uint32_t dst = sb + A_MASK(st);
            #pragma unroll
            for (int j = 0; j < 2; j++) {
                int vec = tid + j * 128;
                int row = vec >> 2, cbt = (vec & 3) * 16;
                cp_async16(dst + row * 64 + cbt, base + (size_t)row * Ss + cbt);
            }
        }
    };

    prefetch(sList[1], 0);
    CP_COMMIT();

    // ---- state ----
    float o[16][4];
    #pragma unroll
    for (int i = 0; i < 16; i++)
        #pragma unroll
        for (int j = 0; j < 4; j++) o[i][j] = 0.0f;
    float m0r = -1e30f, m1r = -1e30f, l0r = 0.0f, l1r = 0.0f;

    int qrow0 = w * 16;
    int r0l = qrow0 + (l >> 2);

    for (int i = 0; i < cnt; i++) {
        int st = i & 1;
        __syncthreads();   // all warps done with stage st^1 (iter i-1) before refill
        if (i + 1 < cnt) {
            prefetch(sList[1 + i + 1], st ^ 1);
            CP_COMMIT();
            CP_WAIT(1);
        } else {
            CP_WAIT(0);
        }
        __syncthreads();

        uint32_t kvb = sb + A_KV(st);

        // ---- S = Q @ K^T (fp16x2) ----
        float s[8][4];
        #pragma unroll
        for (int nt = 0; nt < 8; nt++)
            #pragma unroll
            for (int j = 0; j < 4; j++) s[nt][j] = 0.0f;

        #pragma unroll
        for (int chunk = 0; chunk < 2; chunk++) {
            uint32_t bQh = sb + A_SQ + chunk * 8192;
            uint32_t bQl = sb + A_SQ + 16384 + chunk * 8192;
            uint32_t bKh = kvb + chunk * 8192;
            #pragma unroll
            for (int ks = 0; ks < 4; ks++) {
                int kk = ks * 32;
                int rowA = qrow0 + rrA;
                uint32_t offA = rowA * 128 + ((kk + kbA) ^ ((rowA & 7) << 4));
                uint32_t ah[4], al[4];
                ldsm4(ah, bQh + offA);
                ldsm4(al, bQl + offA);
                #pragma unroll
                for (int np = 0; np < 4; np++) {
                    int rowB = np * 16 + rrB;
                    uint32_t offB = rowB * 128 + ((kk + kbB) ^ ((rowB & 7) << 4));
                    uint32_t th[4];
                    ldsm4(th, bKh + offB);
                    uint32_t bh0[2] = {th[0], th[1]}, bh1[2] = {th[2], th[3]};
                    mma16816(s[np * 2], ah, bh0);
                    mma16816(s[np * 2], al, bh0);
                    mma16816(s[np * 2 + 1], ah, bh1);
                    mma16816(s[np * 2 + 1], al, bh1);
                }
            }
        }

        // ---- mask + scale + online softmax ----
        const unsigned char* mk = (const unsigned char*)(sm + A_MASK(st))
                                  + r0l * 64 + (l & 3) * 2;
        float mx0 = -1e30f, mx1 = -1e30f;
        #pragma unroll
        for (int nt = 0; nt < 8; nt++) {
            int cb = nt * 8;
            float t00 = mk[cb]       ? s[nt][0] * SCALE_F : -1e30f;
            float t01 = mk[cb + 1]   ? s[nt][1] * SCALE_F : -1e30f;
            float t10 = mk[cb + 512] ? s[nt][2] * SCALE_F : -1e30f;
            float t11 = mk[cb + 513] ? s[nt][3] * SCALE_F : -1e30f;
            s[nt][0] = t00; s[nt][1] = t01; s[nt][2] = t10; s[nt][3] = t11;
            mx0 = fmaxf(mx0, fmaxf(t00, t01));
            mx1 = fmaxf(mx1, fmaxf(t10, t11));
        }
        mx0 = fmaxf(mx0, __shfl_xor_sync(0xffffffffu, mx0, 1));
        mx0 = fmaxf(mx0, __shfl_xor_sync(0xffffffffu, mx0, 2));
        mx1 = fmaxf(mx1, __shfl_xor_sync(0xffffffffu, mx1, 1));
        mx1 = fmaxf(mx1, __shfl_xor_sync(0xffffffffu, mx1, 2));
        float mn0 = fmaxf(m0r, mx0), mn1 = fmaxf(m1r, mx1);
        float sc0 = __expf(m0r - mn0), sc1 = __expf(m1r - mn1);
        m0r = mn0; m1r = mn1;

        // ---- P = exp(S - m), write hi/lo fp16 to smem (full-column swizzle) ----
        float sum0 = 0.0f, sum1 = 0.0f;
        int colb = (l & 3) * 4;
        int sw0 = (r0l & 7) << 4;                 // same for r0l and r0l+8
        uint32_t rb0 = r0l * 128;
        uint32_t rb1 = (r0l + 8) * 128;
        #pragma unroll
        for (int nt = 0; nt < 8; nt++) {
            float p00 = __expf(s[nt][0] - mn0);
            float p01 = __expf(s[nt][1] - mn0);
            float p10 = __expf(s[nt][2] - mn1);
            float p11 = __expf(s[nt][3] - mn1);
            sum0 += p00 + p01;
            sum1 += p10 + p11;
            __half h00 = __float2half_rn(p00), h01 = __float2half_rn(p01);
            __half h10 = __float2half_rn(p10), h11 = __float2half_rn(p11);
            uint32_t colsw = (uint32_t)((nt * 16 + colb) ^ sw0);
            uint32_t a0 = rb0 + colsw;
            uint32_t a1 = rb1 + colsw;
            *(uint32_t*)(sm + A_P + a0) = pack_h2(__half2float(h00), __half2float(h01));
            *(uint32_t*)(sm + A_P + a1) = pack_h2(__half2float(h10), __half2float(h11));
            *(uint32_t*)(sm + A_P + 8192 + a0) =
                pack_h2(p00 - __half2float(h00), p01 - __half2float(h01));
            *(uint32_t*)(sm + A_P + 8192 + a1) =
                pack_h2(p10 - __half2float(h10), p11 - __half2float(h11));
        }
        sum0 += __shfl_xor_sync(0xffffffffu, sum0, 1);
        sum0 += __shfl_xor_sync(0xffffffffu, sum0, 2);
        sum1 += __shfl_xor_sync(0xffffffffu, sum1, 1);
        sum1 += __shfl_xor_sync(0xffffffffu, sum1, 2);
        l0r = l0r * sc0 + sum0;
        l1r = l1r * sc1 + sum1;

        // ---- O rescale + O += P @ Vt (fp16x2) ----
        #pragma unroll
        for (int nt = 0; nt < 16; nt++) {
            o[nt][0] *= sc0; o[nt][1] *= sc0;
            o[nt][2] *= sc1; o[nt][3] *= sc1;
        }
        __syncwarp();

        uint32_t bPh = sb + A_P, bPl = sb + A_P + 8192;
        uint32_t bVh = kvb + 16384;
        #pragma unroll
        for (int ks = 0; ks < 4; ks++) {
            int kk = ks * 32;
            int rowA = qrow0 + rrA;
            uint32_t offA = rowA * 128 + ((kk + kbA) ^ ((rowA & 7) << 4));
            uint32_t ph[4], pl[4];
            ldsm4(ph, bPh + offA);
            ldsm4(pl, bPl + offA);
            #pragma unroll
            for (int np = 0; np < 8; np++) {
                int rowB = np * 16 + rrB;
                uint32_t offB = rowB * 128 + ((kk + kbB) ^ ((rowB & 7) << 4));
                uint32_t th[4];
                ldsm4(th, bVh + offB);
                uint32_t vh0[2] = {th[0], th[1]}, vh1[2] = {th[2], th[3]};
                mma16816(o[np * 2], ph, vh0);
                mma16816(o[np * 2], pl, vh0);
                mma16816(o[np * 2 + 1], ph, vh1);
                mma16816(o[np * 2 + 1], pl, vh1);
            }
        }
    }

    // ---- epilogue: O /= l, write ctx hi/lo fp16 ----
    float inv0 = 1.0f / l0r, inv1 = 1.0f / l1r;
    size_t row0 = (size_t)b * Ss + qb * 64 + qrow0 + (l >> 2);
    size_t row1 = row0 + 8;
    int cn0 = h * 128 + (l & 3) * 2;
    #pragma unroll
    for (int nt = 0; nt < 16; nt++) {
        int cn = cn0 + nt * 8;
        float v0 = o[nt][0] * inv0, v1 = o[nt][1] * inv0;
        float v2 = o[nt][2] * inv1, v3 = o[nt][3] * inv1;
        __half h0 = __float2half_rn(v0), h1 = __float2half_rn(v1);
        __half h2 = __float2half_rn(v2), h3 = __float2half_rn(v3);
        size_t i0 = row0 * HIDD + cn, i1 = row1 * HIDD + cn;
        *(uint32_t*)&g_chi[i0] = pack_h2(__half2float(h0), __half2float(h1));
        *(uint32_t*)&g_chi[i1] = pack_h2(__half2float(h2), __half2float(h3));
        *(uint32_t*)&g_clo[i0] = pack_h2(v0 - __half2float(h0), v1 - __half2float(h1));
        *(uint32_t*)&g_clo[i1] = pack_h2(v2 - __half2float(h2), v3 - __half2float(h3));
    }
}

// ---------------- launch ----------------
extern "C" void kernel_launch(void* const* d_in, const int* in_sizes, int n_in,
                              void* d_out, int out_size) {
    const float* X  = (const float*)d_in[0];
    const float* Wq = (const float*)d_in[1];
    const float* Wk = (const float*)d_in[2];
    const float* Wv = (const float*)d_in[3];
    const float* Wo = (const float*)d_in[4];
    const void*  Mraw = d_in[5];
    float* out = (float*)d_out;

    cudaFuncSetAttribute(gemm_qkv,
                         cudaFuncAttributeMaxDynamicSharedMemorySize, GSMEM_TOTAL);
    cudaFuncSetAttribute(gemm_out,
                         cudaFuncAttributeMaxDynamicSharedMemorySize, GSMEM_TOTAL);
    cudaFuncSetAttribute(attn_mma,
                         cudaFuncAttributeMaxDynamicSharedMemorySize, ATTN2_SMEM);

    __half *pxhi, *pxlo;
    cudaGetSymbolAddress((void**)&pxhi, g_xhi);
    cudaGetSymbolAddress((void**)&pxlo, g_xlo);

    // 1: mask detect, 2: expand, 3: bany
    detect_kernel<<<1, 1>>>((const unsigned char*)Mraw);
    expand_kernel<<<(Ss * Ss) / 256, 256>>>(Mraw);
    bany_kernel<<<dim3(NBLK, NBLK), 64>>>();

    // 4: X split, 5: W transposes (batched)
    split_kernel<<<(MROWS * HIDD / 4 + 255) / 256, 256>>>(X, pxhi, pxlo, MROWS * HIDD / 4);
    tsplit4_kernel<<<dim3(HIDD / 32, HIDD / 32, 4), dim3(32, 8)>>>(Wq, Wk, Wv, Wo);

    // 6: batched Q/K/V projections (fp16x2 HMMA)
    gemm_qkv<<<dim3(GN / 128, MROWS / 128, 3), 256, GSMEM_TOTAL>>>();

    // 7: V transpose (fp16)
    vtsplit_kernel<<<dim3(HIDD / 32, MROWS / 32), dim3(32, 8)>>>();

    // 8: attention
    attn_mma<<<dim3(NBLK, Hh, Bb), 128, ATTN2_SMEM>>>();

    // 9: output projection
    gemm_out<<<dim3(GN / 128, MROWS / 128), 256, GSMEM_TOTAL>>>(out);
}

// round 8
// speedup vs baseline: 4.8089x; 1.0252x over previous
#include <cuda_runtime.h>
#include <cuda_fp16.h>
#include <stdint.h>
#include <math.h>

// Problem constants
#define Bb    2
#define Ss    2048
#define HIDD  2048
#define Hh    16
#define DHh   128
#define NBLK  32        // 2048 / 64
#define MROWS 4096      // B*S
#define SCALE_F 0.08838834764831845f   // 1/sqrt(128)

// ---------------- scratch (static device allocations) ----------------
__device__ __half g_xhi[(size_t)MROWS * HIDD];
__device__ __half g_xlo[(size_t)MROWS * HIDD];
__device__ __half g_qhi[(size_t)MROWS * HIDD];
__device__ __half g_qlo[(size_t)MROWS * HIDD];
__device__ __half g_khi[(size_t)MROWS * HIDD];
__device__ __half g_vh [(size_t)MROWS * HIDD];    // V projection, [m][n] fp16
__device__ __half g_vthi[(size_t)MROWS * HIDD];   // [b][h*dh][s]
__device__ __half g_chi[(size_t)MROWS * HIDD];
__device__ __half g_clo[(size_t)MROWS * HIDD];
__device__ __half g_wthi[4][(size_t)HIDD * HIDD];   // W^T [N][K] fp16
__device__ unsigned char g_mask[(size_t)Ss * Ss];
__device__ unsigned char g_bany[NBLK * NBLK];
__device__ int g_flag;

// ======================= PTX helpers (family-portable) =======================
__device__ __forceinline__ uint32_t smem_u32(const void* p) {
    uint32_t a;
    asm("{ .reg .u64 t; cvta.to.shared.u64 t, %1; cvt.u32.u64 %0, t; }"
        : "=r"(a) : "l"(p));
    return a;
}
__device__ __forceinline__ void cp_async16(uint32_t dst, const void* src) {
    asm volatile("cp.async.cg.shared.global [%0], [%1], 16;"
                 :: "r"(dst), "l"(src) : "memory");
}
#define CP_COMMIT() asm volatile("cp.async.commit_group;" ::: "memory")
#define CP_WAIT(n)  asm volatile("cp.async.wait_group %0;" :: "n"(n) : "memory")

__device__ __forceinline__ void ldsm4(uint32_t* r, uint32_t addr) {
    asm volatile("ldmatrix.sync.aligned.m8n8.x4.shared.b16 {%0,%1,%2,%3}, [%4];"
                 : "=r"(r[0]), "=r"(r[1]), "=r"(r[2]), "=r"(r[3]) : "r"(addr));
}
__device__ __forceinline__ void mma16816(float* c, const uint32_t* a, const uint32_t* b) {
    asm volatile(
        "mma.sync.aligned.m16n8k16.row.col.f32.f16.f16.f32 "
        "{%0,%1,%2,%3}, {%4,%5,%6,%7}, {%8,%9}, {%0,%1,%2,%3};"
        : "+f"(c[0]), "+f"(c[1]), "+f"(c[2]), "+f"(c[3])
        : "r"(a[0]), "r"(a[1]), "r"(a[2]), "r"(a[3]), "r"(b[0]), "r"(b[1]));
}

#define SW128(o) ((o) ^ (((o) >> 3) & 0x70))

__device__ __forceinline__ uint32_t pack_h2(float a, float b) {
    __half2 t = __floats2half2_rn(a, b);
    return *(uint32_t*)&t;
}

// ---------------- mask dtype detection + canonicalization ----------------
__global__ void detect_kernel(const unsigned char* __restrict__ raw) {
    int f;
    if (raw[0] == 1 && raw[1] == 1) f = 0;       // u8 / bool
    else if (raw[0] == 1)           f = 1;       // int32
    else                            f = 2;       // float32
    g_flag = f;
}

__global__ void expand_kernel(const void* __restrict__ raw) {
    size_t idx = (size_t)blockIdx.x * blockDim.x + threadIdx.x;
    if (idx >= (size_t)Ss * Ss) return;
    int f = g_flag;
    unsigned char v;
    if (f == 0)      v = ((const unsigned char*)raw)[idx] != 0;
    else if (f == 1) v = ((const int*)raw)[idx] != 0;
    else             v = ((const float*)raw)[idx] != 0.0f;
    g_mask[idx] = v;
}

__global__ void bany_kernel() {
    int qb = blockIdx.y, kb = blockIdx.x;
    int r = threadIdx.x;   // 64 threads
    const unsigned char* row = &g_mask[(size_t)(qb * 64 + r) * Ss + kb * 64];
    int any = 0;
    #pragma unroll 8
    for (int c = 0; c < 64; c++) any |= row[c];
    int res = __syncthreads_or(any);
    if (r == 0) g_bany[qb * NBLK + kb] = res ? 1 : 0;
}

// ---------------- fp32 -> fp16 hi/lo split ----------------
__global__ void split_kernel(const float* __restrict__ in,
                             __half* __restrict__ hi,
                             __half* __restrict__ lo, int n4) {
    int i = blockIdx.x * blockDim.x + threadIdx.x;
    if (i >= n4) return;
    float4 v = ((const float4*)in)[i];
    __half h0 = __float2half_rn(v.x), h1 = __float2half_rn(v.y);
    __half h2 = __float2half_rn(v.z), h3 = __float2half_rn(v.w);
    __half l0 = __float2half_rn(v.x - __half2float(h0));
    __half l1 = __float2half_rn(v.y - __half2float(h1));
    __half l2 = __float2half_rn(v.z - __half2float(h2));
    __half l3 = __float2half_rn(v.w - __half2float(h3));
    ushort4 hv = make_ushort4(__half_as_ushort(h0), __half_as_ushort(h1),
                              __half_as_ushort(h2), __half_as_ushort(h3));
    ushort4 lv = make_ushort4(__half_as_ushort(l0), __half_as_ushort(l1),
                              __half_as_ushort(l2), __half_as_ushort(l3));
    ((ushort4*)hi)[i] = hv;
    ((ushort4*)lo)[i] = lv;
}

// ---------------- batched transpose: W[K][N] -> T[N][K] fp16, z = which W ----
__global__ void tsplit4_kernel(const float* __restrict__ W0,
                               const float* __restrict__ W1,
                               const float* __restrict__ W2,
                               const float* __restrict__ W3) {
    __shared__ float t[32][33];
    int z = blockIdx.z;
    const float* W = (z == 0) ? W0 : (z == 1) ? W1 : (z == 2) ? W2 : W3;
    __half* Thi = g_wthi[z];
    int n0 = blockIdx.x * 32, k0 = blockIdx.y * 32;
    int tx = threadIdx.x, ty = threadIdx.y;   // block (32, 8)
    #pragma unroll
    for (int i = 0; i < 4; i++)
        t[ty + i * 8][tx] = W[(size_t)(k0 + ty + i * 8) * HIDD + n0 + tx];
    __syncthreads();
    #pragma unroll
    for (int i = 0; i < 4; i++)
        Thi[(size_t)(n0 + ty + i * 8) * HIDD + k0 + tx] =
            __float2half_rn(t[tx][ty + i * 8]);
}

// ---------------- transpose V (fp16): g_vh[m][n] -> vt[(b*2048+n)][s] ---------
__global__ void vtsplit_kernel() {
    __shared__ __half t[32][34];
    int n0 = blockIdx.x * 32, m0 = blockIdx.y * 32;
    int tx = threadIdx.x, ty = threadIdx.y;   // block (32, 8)
    #pragma unroll
    for (int i = 0; i < 4; i++)
        t[ty + i * 8][tx] = g_vh[(size_t)(m0 + ty + i * 8) * HIDD + n0 + tx];
    __syncthreads();
    int b = m0 >> 11;
    int s0 = m0 & 2047;
    #pragma unroll
    for (int i = 0; i < 4; i++) {
        size_t o = ((size_t)b * 2048 + n0 + ty + i * 8) * 2048 + s0 + tx;
        g_vthi[o] = t[tx][ty + i * 8];
    }
}

// ---------------- HMMA fp16x2 GEMM core (128x256 CTA tile) ----------------
// C = A @ B^T;  A [M][K] split fp16 hi/lo, B [N][K] K-major fp16.
// C += Ahi*B + Alo*B  (fp32 accum).  3-stage cp.async pipeline.
// 8 warps: warp_m = wid&1 (2), warp_n = wid>>1 (4); warp tile 64x64.
#define GK 2048
#define GN 2048
#define NIT 32
#define GTB_A 16384                       // 128 rows x 128 B
#define GTB_B 32768                       // 256 rows x 128 B
#define GSTAGE (2 * GTB_A + GTB_B)        // 65536
#define GSMEM_TOTAL (3 * GSTAGE)          // 196608

__device__ __forceinline__
void gemm_body(const __half* __restrict__ Ahi,
               const __half* __restrict__ Alo,
               const __half* __restrict__ Bh,
               float* __restrict__ C,
               __half* __restrict__ Chi,
               __half* __restrict__ Clo,
               char* smem) {
    uint32_t sb = smem_u32(smem);
    int tid = threadIdx.x, l = tid & 31, wid = tid >> 5;
    int warp_m = wid & 1, warp_n = wid >> 1;
    int bm = blockIdx.y * 128, bn = blockIdx.x * 256;

    const char* srcAh = (const char*)(Ahi + (size_t)bm * GK);
    const char* srcAl = (const char*)(Alo + (size_t)bm * GK);
    const char* srcB  = (const char*)(Bh + (size_t)bn * GK);

    float c[4][8][4];
    #pragma unroll
    for (int i = 0; i < 4; i++)
        #pragma unroll
        for (int j = 0; j < 8; j++)
            #pragma unroll
            for (int k = 0; k < 4; k++) c[i][j][k] = 0.0f;

    auto stage_load = [&](int ci, int st) {
        int koff = ci * 128;
        uint32_t dstA = sb + st * GSTAGE;
        #pragma unroll
        for (int j = 0; j < 4; j++) {              // Ahi, Alo: 4 vec each
            int vec = tid + j * 256;
            int row = vec >> 3, col = (vec & 7) * 16;
            uint32_t so = SW128(row * 128 + col);
            const char* s = srcAh + (size_t)row * (GK * 2) + koff + col;
            cp_async16(dstA + so, s);
            cp_async16(dstA + GTB_A + so, srcAl + (size_t)row * (GK * 2) + koff + col);
        }
        uint32_t dstB = dstA + 2 * GTB_A;
        #pragma unroll
        for (int j = 0; j < 8; j++) {              // B: 8 vec
            int vec = tid + j * 256;
            int row = vec >> 3, col = (vec & 7) * 16;
            cp_async16(dstB + SW128(row * 128 + col),
                       srcB + (size_t)row * (GK * 2) + koff + col);
        }
    };

    int rrA = (l & 7) + ((l >> 3) & 1) * 8;
    int kbA = ((l >> 4) & 1) * 16;
    int rrB = (l & 7) + ((l >> 4) & 1) * 8;
    int kbB = ((l >> 3) & 1) * 16;

    stage_load(0, 0);
    CP_COMMIT();
    stage_load(1, 1);
    CP_COMMIT();

    for (int i = 0; i < NIT; i++) {
        __syncthreads();   // protect slot (i+2)%3 (consumed at iter i-1)
        if (i + 2 < NIT) {
            stage_load(i + 2, (i + 2) % 3);
            CP_COMMIT();
            CP_WAIT(2);
        } else if (i + 1 < NIT) {
            CP_WAIT(1);
        } else {
            CP_WAIT(0);
        }
        __syncthreads();

        uint32_t bAh = sb + (i % 3) * GSTAGE;
        uint32_t bAl = bAh + GTB_A;
        uint32_t bBh = bAh + 2 * GTB_A;

        #pragma unroll
        for (int ks = 0; ks < 4; ks++) {
            int kk = ks * 32;
            uint32_t afh[4][4], afl[4][4];
            #pragma unroll
            for (int mt = 0; mt < 4; mt++) {
                int rb = (warp_m * 64 + mt * 16 + rrA) * 128;
                uint32_t off = rb + ((kk + kbA) ^ ((rb >> 3) & 0x70));
                ldsm4(afh[mt], bAh + off);
                ldsm4(afl[mt], bAl + off);
            }
            uint32_t bf[8][2];
            #pragma unroll
            for (int np = 0; np < 4; np++) {
                int rb = (warp_n * 64 + np * 16 + rrB) * 128;
                uint32_t off = rb + ((kk + kbB) ^ ((rb >> 3) & 0x70));
                uint32_t t[4];
                ldsm4(t, bBh + off);
                bf[np * 2][0] = t[0]; bf[np * 2][1] = t[1];
                bf[np * 2 + 1][0] = t[2]; bf[np * 2 + 1][1] = t[3];
            }
            #pragma unroll
            for (int mt = 0; mt < 4; mt++)
                #pragma unroll
                for (int nt = 0; nt < 8; nt++) {
                    mma16816(c[mt][nt], afh[mt], bf[nt]);
                    mma16816(c[mt][nt], afl[mt], bf[nt]);
                }
        }
    }

    // epilogue
    #pragma unroll
    for (int mt = 0; mt < 4; mt++) {
        #pragma unroll
        for (int nt = 0; nt < 8; nt++) {
            int m0 = bm + warp_m * 64 + mt * 16 + (l >> 2);
            int cn = bn + warp_n * 64 + nt * 8 + (l & 3) * 2;
            size_t i0 = (size_t)m0 * GN + cn, i1 = (size_t)(m0 + 8) * GN + cn;
            float v0 = c[mt][nt][0], v1 = c[mt][nt][1];
            float v2 = c[mt][nt][2], v3 = c[mt][nt][3];
            if (Chi) {
                __half h0 = __float2half_rn(v0), h1 = __float2half_rn(v1);
                __half h2 = __float2half_rn(v2), h3 = __float2half_rn(v3);
                *(uint32_t*)&Chi[i0] = pack_h2(__half2float(h0), __half2float(h1));
                *(uint32_t*)&Chi[i1] = pack_h2(__half2float(h2), __half2float(h3));
                if (Clo) {
                    *(uint32_t*)&Clo[i0] = pack_h2(v0 - __half2float(h0), v1 - __half2float(h1));
                    *(uint32_t*)&Clo[i1] = pack_h2(v2 - __half2float(h2), v3 - __half2float(h3));
                }
            } else {
                *(float2*)&C[i0] = make_float2(v0, v1);
                *(float2*)&C[i1] = make_float2(v2, v3);
            }
        }
    }
}

// batched QKV projection: z=0 -> Q (hi/lo), z=1 -> K (hi), z=2 -> V (hi)
__global__ __launch_bounds__(256, 1)
void gemm_qkv() {
    extern __shared__ char smem[];
    int z = blockIdx.z;
    const __half* B = g_wthi[z];
    __half* Chi = (z == 0) ? g_qhi : (z == 1) ? g_khi : g_vh;
    __half* Clo = (z == 0) ? g_qlo : nullptr;
    gemm_body(g_xhi, g_xlo, B, nullptr, Chi, Clo, smem);
}

// output projection: fp32 out
__global__ __launch_bounds__(256, 1)
void gemm_out(float* __restrict__ C) {
    extern __shared__ char smem[];
    gemm_body(g_chi, g_clo, g_wthi[3], C, nullptr, nullptr, smem);
}

// ---------------- HMMA fp16x2 flash attention ----------------
// grid (qb=32, h=16, b=2), 128 threads (4 warps). Warp w owns q rows [w*16, w*16+16).
// S = Qhi·K + Qlo·K ; O += Phi·V + Plo·V (K, V fp16 hi only)
#define A_SQ       0                       // Q: hi c0, hi c1, lo c0, lo c1 (4 x 8KB)
#define A_KV(st)   (32768 + (st) * 32768)  // Khi c0 (8KB), Khi c1 (8KB), Vhi (16KB)
#define A_P        98304                   // Phi 8KB, Plo 8KB
#define A_MASK(st) (114688 + (st) * 4096)
#define A_LIST     122880                  // int count + int[32]
#define ATTN2_SMEM 123136

__global__ __launch_bounds__(128, 1)
void attn_mma() {
    extern __shared__ char sm[];
    uint32_t sb = smem_u32(sm);
    int tid = threadIdx.x, l = tid & 31, w = tid >> 5;
    int qb = blockIdx.x, h = blockIdx.y, b = blockIdx.z;

    int rrA = (l & 7) + ((l >> 3) & 1) * 8;
    int kbA = ((l >> 4) & 1) * 16;
    int rrB = (l & 7) + ((l >> 4) & 1) * 8;
    int kbB = ((l >> 3) & 1) * 16;

    const size_t qrow_base = ((size_t)b * Ss + qb * 64) * HIDD;   // elements
    const size_t colb_base = (size_t)h * 256;                     // bytes within row

    // ---- load Q tiles (hi c0, hi c1, lo c0, lo c1) ----
    {
        #pragma unroll
        for (int t = 0; t < 4; t++) {
            const char* base = (const char*)((t < 2) ? g_qhi : g_qlo) + qrow_base * 2
                               + colb_base + (t & 1) * 128;
            uint32_t dst = sb + A_SQ + t * 8192;
            #pragma unroll
            for (int j = 0; j < 4; j++) {
                int vec = tid + j * 128;
                int row = vec >> 3, cbt = (vec & 7) * 16;
                cp_async16(dst + SW128(row * 128 + cbt),
                           base + (size_t)row * 4096 + cbt);
            }
        }
        CP_COMMIT();
    }

    // ---- build visible-kb list ----
    int* sList = (int*)(sm + A_LIST);
    if (tid == 0) {
        int c = 0;
        for (int kb = 0; kb < NBLK; kb++)
            if (g_bany[qb * NBLK + kb]) sList[1 + c++] = kb;
        sList[0] = c;
    }
    __syncthreads();
    int cnt = sList[0];

    // ---- KV + mask prefetch ----
    auto prefetch = [&](int kb, int st) {
        uint32_t kvb = sb + A_KV(st);
        size_t krow = ((size_t)b * Ss + kb * 64) * HIDD * 2;   // bytes
        #pragma unroll
        for (int t = 0; t < 2; t++) {     // Khi chunk 0, chunk 1
            const char* base = (const char*)g_khi + krow + colb_base + t * 128;
            uint32_t dst = kvb + t * 8192;
            #pragma unroll
            for (int j = 0; j < 4; j++) {
                int vec = tid + j * 128;
                int row = vec >> 3, cbt = (vec & 7) * 16;
                cp_async16(dst + SW128(row * 128 + cbt),
                           base + (size_t)row * 4096 + cbt);
            }
        }
        size_t vrow = ((size_t)b * 2048 + h * 128) * 2048 * 2;  // bytes; +dh*4096
        {
            const char* base = (const char*)g_vthi + vrow + kb * 128;
            uint32_t dst = kvb + 16384;
            #pragma unroll
            for (int j = 0; j < 8; j++) {
                int vec = tid + j * 128;
                int row = vec >> 3, cbt = (vec & 7) * 16;
                cp_async16(dst + SW128(row * 128 + cbt),
                           base + (size_t)row * 4096 + cbt);
            }
        }
        {
            const char* base = (const char*)g_mask + (size_t)(qb * 64) * Ss + kb * 64;
            uint32_t dst = sb + A_MASK(st);
            #pragma unroll
            for (int j = 0; j < 2; j++) {
                int vec = tid + j * 128;
                int row = vec >> 2, cbt = (vec & 3) * 16;
                cp_async16(dst + row * 64 + cbt, base + (size_t)row * Ss + cbt);
            }
        }
    };

    prefetch(sList[1], 0);
    CP_COMMIT();

    // ---- state ----
    float o[16][4];
    #pragma unroll
    for (int i = 0; i < 16; i++)
        #pragma unroll
        for (int j = 0; j < 4; j++) o[i][j] = 0.0f;
    float m0r = -1e30f, m1r = -1e30f, l0r = 0.0f, l1r = 0.0f;

    int qrow0 = w * 16;
    int r0l = qrow0 + (l >> 2);

    for (int i = 0; i < cnt; i++) {
        int st = i & 1;
        __syncthreads();   // all warps done with stage st^1 (iter i-1) before refill
        if (i + 1 < cnt) {
            prefetch(sList[1 + i + 1], st ^ 1);
            CP_COMMIT();
            CP_WAIT(1);
        } else {
            CP_WAIT(0);
        }
        __syncthreads();

        uint32_t kvb = sb + A_KV(st);

        // ---- S = Q @ K^T (fp16x2) ----
        float s[8][4];
        #pragma unroll
        for (int nt = 0; nt < 8; nt++)
            #pragma unroll
            for (int j = 0; j < 4; j++) s[nt][j] = 0.0f;

        #pragma unroll
        for (int chunk = 0; chunk < 2; chunk++) {
            uint32_t bQh = sb + A_SQ + chunk * 8192;
            uint32_t bQl = sb + A_SQ + 16384 + chunk * 8192;
            uint32_t bKh = kvb + chunk * 8192;
            #pragma unroll
            for (int ks = 0; ks < 4; ks++) {
                int kk = ks * 32;
                int rowA = qrow0 + rrA;
                uint32_t offA = rowA * 128 + ((kk + kbA) ^ ((rowA & 7) << 4));
                uint32_t ah[4], al[4];
                ldsm4(ah, bQh + offA);
                ldsm4(al, bQl + offA);
                #pragma unroll
                for (int np = 0; np < 4; np++) {
                    int rowB = np * 16 + rrB;
                    uint32_t offB = rowB * 128 + ((kk + kbB) ^ ((rowB & 7) << 4));
                    uint32_t th[4];
                    ldsm4(th, bKh + offB);
                    uint32_t bh0[2] = {th[0], th[1]}, bh1[2] = {th[2], th[3]};
                    mma16816(s[np * 2], ah, bh0);
                    mma16816(s[np * 2], al, bh0);
                    mma16816(s[np * 2 + 1], ah, bh1);
                    mma16816(s[np * 2 + 1], al, bh1);
                }
            }
        }

        // ---- mask + scale + online softmax ----
        const unsigned char* mk = (const unsigned char*)(sm + A_MASK(st))
                                  + r0l * 64 + (l & 3) * 2;
        float mx0 = -1e30f, mx1 = -1e30f;
        #pragma unroll
        for (int nt = 0; nt < 8; nt++) {
            int cb = nt * 8;
            float t00 = mk[cb]       ? s[nt][0] * SCALE_F : -1e30f;
            float t01 = mk[cb + 1]   ? s[nt][1] * SCALE_F : -1e30f;
            float t10 = mk[cb + 512] ? s[nt][2] * SCALE_F : -1e30f;
            float t11 = mk[cb + 513] ? s[nt][3] * SCALE_F : -1e30f;
            s[nt][0] = t00; s[nt][1] = t01; s[nt][2] = t10; s[nt][3] = t11;
            mx0 = fmaxf(mx0, fmaxf(t00, t01));
            mx1 = fmaxf(mx1, fmaxf(t10, t11));
        }
        mx0 = fmaxf(mx0, __shfl_xor_sync(0xffffffffu, mx0, 1));
        mx0 = fmaxf(mx0, __shfl_xor_sync(0xffffffffu, mx0, 2));
        mx1 = fmaxf(mx1, __shfl_xor_sync(0xffffffffu, mx1, 1));
        mx1 = fmaxf(mx1, __shfl_xor_sync(0xffffffffu, mx1, 2));
        float mn0 = fmaxf(m0r, mx0), mn1 = fmaxf(m1r, mx1);
        float sc0 = __expf(m0r - mn0), sc1 = __expf(m1r - mn1);
        m0r = mn0; m1r = mn1;

        // ---- P = exp(S - m), write hi/lo fp16 to smem (full-column swizzle) ----
        float sum0 = 0.0f, sum1 = 0.0f;
        int colb = (l & 3) * 4;
        int sw0 = (r0l & 7) << 4;                 // same for r0l and r0l+8
        uint32_t rb0 = r0l * 128;
        uint32_t rb1 = (r0l + 8) * 128;
        #pragma unroll
        for (int nt = 0; nt < 8; nt++) {
            float p00 = __expf(s[nt][0] - mn0);
            float p01 = __expf(s[nt][1] - mn0);
            float p10 = __expf(s[nt][2] - mn1);
            float p11 = __expf(s[nt][3] - mn1);
            sum0 += p00 + p01;
            sum1 += p10 + p11;
            __half h00 = __float2half_rn(p00), h01 = __float2half_rn(p01);
            __half h10 = __float2half_rn(p10), h11 = __float2half_rn(p11);
            uint32_t colsw = (uint32_t)((nt * 16 + colb) ^ sw0);
            uint32_t a0 = rb0 + colsw;
            uint32_t a1 = rb1 + colsw;
            *(uint32_t*)(sm + A_P + a0) = pack_h2(__half2float(h00), __half2float(h01));
            *(uint32_t*)(sm + A_P + a1) = pack_h2(__half2float(h10), __half2float(h11));
            *(uint32_t*)(sm + A_P + 8192 + a0) =
                pack_h2(p00 - __half2float(h00), p01 - __half2float(h01));
            *(uint32_t*)(sm + A_P + 8192 + a1) =
                pack_h2(p10 - __half2float(h10), p11 - __half2float(h11));
        }
        sum0 += __shfl_xor_sync(0xffffffffu, sum0, 1);
        sum0 += __shfl_xor_sync(0xffffffffu, sum0, 2);
        sum1 += __shfl_xor_sync(0xffffffffu, sum1, 1);
        sum1 += __shfl_xor_sync(0xffffffffu, sum1, 2);
        l0r = l0r * sc0 + sum0;
        l1r = l1r * sc1 + sum1;

        // ---- O rescale + O += P @ Vt (fp16x2) ----
        #pragma unroll
        for (int nt = 0; nt < 16; nt++) {
            o[nt][0] *= sc0; o[nt][1] *= sc0;
            o[nt][2] *= sc1; o[nt][3] *= sc1;
        }
        __syncwarp();

        uint32_t bPh = sb + A_P, bPl = sb + A_P + 8192;
        uint32_t bVh = kvb + 16384;
        #pragma unroll
        for (int ks = 0; ks < 4; ks++) {
            int kk = ks * 32;
            int rowA = qrow0 + rrA;
            uint32_t offA = rowA * 128 + ((kk + kbA) ^ ((rowA & 7) << 4));
            uint32_t ph[4], pl[4];
            ldsm4(ph, bPh + offA);
            ldsm4(pl, bPl + offA);
            #pragma unroll
            for (int np = 0; np < 8; np++) {
                int rowB = np * 16 + rrB;
                uint32_t offB = rowB * 128 + ((kk + kbB) ^ ((rowB & 7) << 4));
                uint32_t th[4];
                ldsm4(th, bVh + offB);
                uint32_t vh0[2] = {th[0], th[1]}, vh1[2] = {th[2], th[3]};
                mma16816(o[np * 2], ph, vh0);
                mma16816(o[np * 2], pl, vh0);
                mma16816(o[np * 2 + 1], ph, vh1);
                mma16816(o[np * 2 + 1], pl, vh1);
            }
        }
    }

    // ---- epilogue: O /= l, write ctx hi/lo fp16 ----
    float inv0 = 1.0f / l0r, inv1 = 1.0f / l1r;
    size_t row0 = (size_t)b * Ss + qb * 64 + qrow0 + (l >> 2);
    size_t row1 = row0 + 8;
    int cn0 = h * 128 + (l & 3) * 2;
    #pragma unroll
    for (int nt = 0; nt < 16; nt++) {
        int cn = cn0 + nt * 8;
        float v0 = o[nt][0] * inv0, v1 = o[nt][1] * inv0;
        float v2 = o[nt][2] * inv1, v3 = o[nt][3] * inv1;
        __half h0 = __float2half_rn(v0), h1 = __float2half_rn(v1);
        __half h2 = __float2half_rn(v2), h3 = __float2half_rn(v3);
        size_t i0 = row0 * HIDD + cn, i1 = row1 * HIDD + cn;
        *(uint32_t*)&g_chi[i0] = pack_h2(__half2float(h0), __half2float(h1));
        *(uint32_t*)&g_chi[i1] = pack_h2(__half2float(h2), __half2float(h3));
        *(uint32_t*)&g_clo[i0] = pack_h2(v0 - __half2float(h0), v1 - __half2float(h1));
        *(uint32_t*)&g_clo[i1] = pack_h2(v2 - __half2float(h2), v3 - __half2float(h3));
    }
}

// ---------------- launch ----------------
extern "C" void kernel_launch(void* const* d_in, const int* in_sizes, int n_in,
                              void* d_out, int out_size) {
    const float* X  = (const float*)d_in[0];
    const float* Wq = (const float*)d_in[1];
    const float* Wk = (const float*)d_in[2];
    const float* Wv = (const float*)d_in[3];
    const float* Wo = (const float*)d_in[4];
    const void*  Mraw = d_in[5];
    float* out = (float*)d_out;

    cudaFuncSetAttribute(gemm_qkv,
                         cudaFuncAttributeMaxDynamicSharedMemorySize, GSMEM_TOTAL);
    cudaFuncSetAttribute(gemm_out,
                         cudaFuncAttributeMaxDynamicSharedMemorySize, GSMEM_TOTAL);
    cudaFuncSetAttribute(attn_mma,
                         cudaFuncAttributeMaxDynamicSharedMemorySize, ATTN2_SMEM);

    __half *pxhi, *pxlo;
    cudaGetSymbolAddress((void**)&pxhi, g_xhi);
    cudaGetSymbolAddress((void**)&pxlo, g_xlo);

    // 1: mask detect, 2: expand, 3: bany
    detect_kernel<<<1, 1>>>((const unsigned char*)Mraw);
    expand_kernel<<<(Ss * Ss) / 256, 256>>>(Mraw);
    bany_kernel<<<dim3(NBLK, NBLK), 64>>>();

    // 4: X split, 5: W transposes (batched)
    split_kernel<<<(MROWS * HIDD / 4 + 255) / 256, 256>>>(X, pxhi, pxlo, MROWS * HIDD / 4);
    tsplit4_kernel<<<dim3(HIDD / 32, HIDD / 32, 4), dim3(32, 8)>>>(Wq, Wk, Wv, Wo);

    // 6: batched Q/K/V projections (fp16x2 HMMA, 128x256 tiles)
    gemm_qkv<<<dim3(GN / 256, MROWS / 128, 3), 256, GSMEM_TOTAL>>>();

    // 7: V transpose (fp16)
    vtsplit_kernel<<<dim3(HIDD / 32, MROWS / 32), dim3(32, 8)>>>();

    // 8: attention
    attn_mma<<<dim3(NBLK, Hh, Bb), 128, ATTN2_SMEM>>>();

    // 9: output projection
    gemm_out<<<dim3(GN / 256, MROWS / 128), 256, GSMEM_TOTAL>>>(out);
}